// round 1
// baseline (speedup 1.0000x reference)
#include <cuda_runtime.h>

// Problem constants
#define CC   64          // channels
#define NN   4096        // pixels per region (64x64)
#define BRN  8           // B*R = 2*4
#define HW   128

// ---------------- scratch (static __device__ allocations; no cudaMalloc) ----
__device__ float g_q[BRN * CC * NN];
__device__ float g_k[BRN * CC * NN];
__device__ float g_a[BRN * CC * NN];
__device__ float g_b[BRN * CC * NN];
__device__ float g_S[(size_t)BRN * NN * NN];   // 512 MB raw scores (already /8)
__device__ float g_M[BRN * NN];                // row max
__device__ float g_R[BRN * NN];                // 1 / row sum-exp

// ============================================================================
// Kernel 1: q,k,a,b = 1x1 convs, written in regionized layout [br][c][n]
//   region r = (h/64)*2 + (w/64), n = (h%64)*64 + (w%64)
// Each block: one (br, 64-pixel image-row chunk). threads: 4 convs x 64 px.
// ============================================================================
__global__ __launch_bounds__(256) void conv_qkab_kernel(
    const float* __restrict__ x,
    const float* __restrict__ Wq, const float* __restrict__ bq,
    const float* __restrict__ Wk, const float* __restrict__ bk,
    const float* __restrict__ Wa, const float* __restrict__ ba,
    const float* __restrict__ Wb, const float* __restrict__ bb)
{
    __shared__ float xs[64 * 64];   // [c][px]
    int blk   = blockIdx.x;         // 0..511
    int br    = blk >> 6;           // 0..7
    int chunk = blk & 63;           // row within region
    int b = br >> 2, r = br & 3;
    int n0 = chunk << 6;
    int h  = ((r >> 1) << 6) + chunk;
    int wb = (r & 1) << 6;

    const float* xrow = x + (size_t)(b * CC) * (HW * HW) + (size_t)h * HW + wb;
    for (int idx = threadIdx.x; idx < 64 * 64; idx += 256) {
        int c = idx >> 6, px = idx & 63;
        xs[idx] = xrow[(size_t)c * (HW * HW) + px];
    }
    __syncthreads();

    int px   = threadIdx.x & 63;
    int conv = threadIdx.x >> 6;    // 0..3
    const float *W, *bi;
    float* outp;
    switch (conv) {
        case 0:  W = Wq; bi = bq; outp = g_q; break;
        case 1:  W = Wk; bi = bk; outp = g_k; break;
        case 2:  W = Wa; bi = ba; outp = g_a; break;
        default: W = Wb; bi = bb; outp = g_b; break;
    }

    float acc[64];
    #pragma unroll
    for (int o = 0; o < 64; o++) acc[o] = bi[o];

    for (int c = 0; c < 64; c++) {
        float xv = xs[(c << 6) + px];
        #pragma unroll
        for (int o = 0; o < 64; o++) acc[o] += W[o * 64 + c] * xv;
    }

    size_t base = (size_t)br * CC * NN + n0 + px;
    #pragma unroll
    for (int o = 0; o < 64; o++) outp[base + (size_t)o * NN] = acc[o];
}

// ============================================================================
// Kernel 2: S[br][n][m] = (q[:,n] . k[:,m]) / 8
// 128x128 block tile, 8x8 per-thread register tile, K = 64 fully in smem.
// ============================================================================
__global__ __launch_bounds__(256) void score_kernel()
{
    extern __shared__ float sm2[];
    float* qs = sm2;              // [64][128]
    float* ks = sm2 + 64 * 128;   // [64][128]

    int mt = blockIdx.x, nt = blockIdx.y, br = blockIdx.z;
    int m0 = mt << 7, n0 = nt << 7;
    const float* qg = g_q + (size_t)br * CC * NN;
    const float* kg = g_k + (size_t)br * CC * NN;

    for (int idx = threadIdx.x; idx < 64 * 128; idx += 256) {
        int c = idx >> 7, i = idx & 127;
        qs[idx] = qg[(size_t)c * NN + n0 + i];
        ks[idx] = kg[(size_t)c * NN + m0 + i];
    }
    __syncthreads();

    int ty = threadIdx.x >> 4, tx = threadIdx.x & 15;
    float acc[8][8];
    #pragma unroll
    for (int i = 0; i < 8; i++)
        #pragma unroll
        for (int j = 0; j < 8; j++) acc[i][j] = 0.f;

    #pragma unroll 4
    for (int c = 0; c < 64; c++) {
        float4 q0 = *(const float4*)&qs[(c << 7) + (ty << 3)];
        float4 q1 = *(const float4*)&qs[(c << 7) + (ty << 3) + 4];
        float4 k0 = *(const float4*)&ks[(c << 7) + (tx << 3)];
        float4 k1 = *(const float4*)&ks[(c << 7) + (tx << 3) + 4];
        float qv[8] = {q0.x, q0.y, q0.z, q0.w, q1.x, q1.y, q1.z, q1.w};
        float kv[8] = {k0.x, k0.y, k0.z, k0.w, k1.x, k1.y, k1.z, k1.w};
        #pragma unroll
        for (int i = 0; i < 8; i++)
            #pragma unroll
            for (int j = 0; j < 8; j++) acc[i][j] += qv[i] * kv[j];
    }

    float* Sb = g_S + (size_t)br * NN * NN + (size_t)(n0 + (ty << 3)) * NN
              + m0 + (tx << 3);
    #pragma unroll
    for (int i = 0; i < 8; i++) {
        float4 s0 = make_float4(acc[i][0] * 0.125f, acc[i][1] * 0.125f,
                                acc[i][2] * 0.125f, acc[i][3] * 0.125f);
        float4 s1 = make_float4(acc[i][4] * 0.125f, acc[i][5] * 0.125f,
                                acc[i][6] * 0.125f, acc[i][7] * 0.125f);
        *(float4*)&Sb[(size_t)i * NN]     = s0;
        *(float4*)&Sb[(size_t)i * NN + 4] = s1;
    }
}

// ============================================================================
// Kernel 3: per-row softmax stats: M[row], R[row] = 1/sum(exp(S-M))
// One block (128 threads) per row.
// ============================================================================
__global__ __launch_bounds__(128) void stats_kernel()
{
    int row = blockIdx.x;                       // 0 .. BRN*NN-1
    const float* Srow = g_S + (size_t)row * NN;
    int t = threadIdx.x, lane = t & 31, warp = t >> 5;

    float v[32];
    float mx = -1e30f;
    #pragma unroll
    for (int i = 0; i < 32; i++) {
        v[i] = Srow[t + (i << 7)];
        mx = fmaxf(mx, v[i]);
    }
    #pragma unroll
    for (int off = 16; off; off >>= 1)
        mx = fmaxf(mx, __shfl_xor_sync(0xffffffffu, mx, off));

    __shared__ float sred[4];
    if (lane == 0) sred[warp] = mx;
    __syncthreads();
    mx = fmaxf(fmaxf(sred[0], sred[1]), fmaxf(sred[2], sred[3]));

    float s = 0.f;
    #pragma unroll
    for (int i = 0; i < 32; i++) s += __expf(v[i] - mx);
    #pragma unroll
    for (int off = 16; off; off >>= 1)
        s += __shfl_xor_sync(0xffffffffu, s, off);

    __syncthreads();
    if (lane == 0) sred[warp] = s;
    __syncthreads();
    if (t == 0) {
        float tot = sred[0] + sred[1] + sred[2] + sred[3];
        g_M[row] = mx;
        g_R[row] = 1.f / tot;
    }
}

// ============================================================================
// Kernel 4: out[c,m] = sum_j Pt[j,m]*a[c,j] + sum_j Pt[m,j]*b[c,j]
//           (Pt[n,m] = exp(S[n,m]-M[n])/D[n]), then fused Wo conv +
//           de-regionize straight into d_out.
// Block = (br, 128-col m-tile). Streams 32 n-tiles of 128.
// ============================================================================
#define P_STRIDE  132
#define AB_STRIDE 68

__global__ __launch_bounds__(256) void out_kernel(
    const float* __restrict__ Wo, const float* __restrict__ bo,
    float* __restrict__ outp)
{
    extern __shared__ float sm4[];
    float* P1  = sm4;                       // [128 j][132]  Pt[n0+j][m0+m]
    float* P2  = P1 + 128 * P_STRIDE;       // [128 j][132]  Pt[m0+i][n0+j] at [j][i]
    float* aT  = P2 + 128 * P_STRIDE;       // [128 j][68]   a[c][n0+j] at [j][c]
    float* bT  = aT + 128 * AB_STRIDE;      // [128 j][68]
    float* Mn  = bT + 128 * AB_STRIDE;      // 128
    float* Rn  = Mn + 128;
    float* Mm  = Rn + 128;
    float* Rm  = Mm + 128;
    float* WoT = Rm + 128;                  // [64 c][68]  Wo[o][c] at [c][o]
    float* bos = WoT + 64 * AB_STRIDE;      // 64

    int mt = blockIdx.x;        // 0..31
    int br = blockIdx.y;        // 0..7
    int m0 = mt << 7;
    int tid = threadIdx.x;

    const float* Sg = g_S + (size_t)br * NN * NN;
    const float* ag = g_a + (size_t)br * CC * NN;
    const float* bg = g_b + (size_t)br * CC * NN;

    if (tid < 128) {
        Mm[tid] = g_M[br * NN + m0 + tid];
        Rm[tid] = g_R[br * NN + m0 + tid];
    }
    for (int idx = tid; idx < 64 * 64; idx += 256) {
        int o = idx >> 6, c = idx & 63;
        WoT[c * AB_STRIDE + o] = Wo[idx];
    }
    if (tid < 64) bos[tid] = bo[tid];

    int cg = tid >> 4;          // c0 = cg*4
    int mg = tid & 15;          // mm0 = mg*8
    float acc[4][8];
    #pragma unroll
    for (int i = 0; i < 4; i++)
        #pragma unroll
        for (int j = 0; j < 8; j++) acc[i][j] = 0.f;

    for (int nt = 0; nt < 32; nt++) {
        int n0 = nt << 7;
        __syncthreads();   // previous iter's GEMM reads complete
        if (tid < 128) {
            Mn[tid] = g_M[br * NN + n0 + tid];
            Rn[tid] = g_R[br * NN + n0 + tid];
        }
        for (int idx = tid; idx < 64 * 128; idx += 256) {
            int c = idx >> 7, j = idx & 127;
            aT[j * AB_STRIDE + c] = ag[(size_t)c * NN + n0 + j];
            bT[j * AB_STRIDE + c] = bg[(size_t)c * NN + n0 + j];
        }
        __syncthreads();
        // P1[j][m] = exp(S[n0+j][m0+m] - Mn[j]) * Rn[j]
        for (int idx = tid; idx < 128 * 128; idx += 256) {
            int j = idx >> 7, m = idx & 127;
            float s = Sg[(size_t)(n0 + j) * NN + m0 + m];
            P1[j * P_STRIDE + m] = __expf(s - Mn[j]) * Rn[j];
        }
        // P2[j][i] = exp(S[m0+i][n0+j] - Mm[i]) * Rm[i]
        for (int idx = tid; idx < 128 * 128; idx += 256) {
            int i = idx >> 7, j = idx & 127;
            float s = Sg[(size_t)(m0 + i) * NN + n0 + j];
            P2[j * P_STRIDE + i] = __expf(s - Mm[i]) * Rm[i];
        }
        __syncthreads();

        #pragma unroll 2
        for (int j = 0; j < 128; j++) {
            float4 p1a = *(const float4*)&P1[j * P_STRIDE + (mg << 3)];
            float4 p1b = *(const float4*)&P1[j * P_STRIDE + (mg << 3) + 4];
            float4 p2a = *(const float4*)&P2[j * P_STRIDE + (mg << 3)];
            float4 p2b = *(const float4*)&P2[j * P_STRIDE + (mg << 3) + 4];
            float4 av  = *(const float4*)&aT[j * AB_STRIDE + (cg << 2)];
            float4 bv  = *(const float4*)&bT[j * AB_STRIDE + (cg << 2)];
            float a_[4] = {av.x, av.y, av.z, av.w};
            float b_[4] = {bv.x, bv.y, bv.z, bv.w};
            float p1_[8] = {p1a.x, p1a.y, p1a.z, p1a.w, p1b.x, p1b.y, p1b.z, p1b.w};
            float p2_[8] = {p2a.x, p2a.y, p2a.z, p2a.w, p2b.x, p2b.y, p2b.z, p2b.w};
            #pragma unroll
            for (int i = 0; i < 4; i++)
                #pragma unroll
                for (int jj = 0; jj < 8; jj++)
                    acc[i][jj] += a_[i] * p1_[jj] + b_[i] * p2_[jj];
        }
    }

    // ---- fused final 1x1 conv (Wo) + de-regionized store ----
    __syncthreads();           // GEMM reads of P1 done; reuse as out_s[c][m]
    #pragma unroll
    for (int i = 0; i < 4; i++)
        #pragma unroll
        for (int jj = 0; jj < 8; jj++)
            P1[(cg * 4 + i) * P_STRIDE + (mg << 3) + jj] = acc[i][jj];
    __syncthreads();

    float fo[4][8];
    #pragma unroll
    for (int i = 0; i < 4; i++) {
        float bv = bos[cg * 4 + i];
        #pragma unroll
        for (int jj = 0; jj < 8; jj++) fo[i][jj] = bv;
    }
    #pragma unroll 4
    for (int c = 0; c < 64; c++) {
        float4 wv = *(const float4*)&WoT[c * AB_STRIDE + (cg << 2)];
        float w_[4] = {wv.x, wv.y, wv.z, wv.w};
        float4 o0 = *(const float4*)&P1[c * P_STRIDE + (mg << 3)];
        float4 o1 = *(const float4*)&P1[c * P_STRIDE + (mg << 3) + 4];
        float ov[8] = {o0.x, o0.y, o0.z, o0.w, o1.x, o1.y, o1.z, o1.w};
        #pragma unroll
        for (int i = 0; i < 4; i++)
            #pragma unroll
            for (int jj = 0; jj < 8; jj++)
                fo[i][jj] += w_[i] * ov[jj];
    }

    int b = br >> 2, r = br & 3;
    #pragma unroll
    for (int i = 0; i < 4; i++) {
        int o = cg * 4 + i;
        #pragma unroll
        for (int jj = 0; jj < 8; jj++) {
            int n = m0 + (mg << 3) + jj;
            int h = ((r >> 1) << 6) + (n >> 6);
            int w = ((r & 1) << 6) + (n & 63);
            outp[(((size_t)(b * 64 + o)) << 14) + (h << 7) + w] = fo[i][jj];
        }
    }
}

// ============================================================================
extern "C" void kernel_launch(void* const* d_in, const int* in_sizes, int n_in,
                              void* d_out, int out_size)
{
    const float* x  = (const float*)d_in[0];
    const float* Wq = (const float*)d_in[1];
    const float* bq = (const float*)d_in[2];
    const float* Wk = (const float*)d_in[3];
    const float* bk = (const float*)d_in[4];
    const float* Wa = (const float*)d_in[5];
    const float* ba = (const float*)d_in[6];
    const float* Wb = (const float*)d_in[7];
    const float* bb = (const float*)d_in[8];
    const float* Wo = (const float*)d_in[9];
    const float* bo = (const float*)d_in[10];

    cudaFuncSetAttribute(score_kernel,
                         cudaFuncAttributeMaxDynamicSharedMemorySize, 65536);
    cudaFuncSetAttribute(out_kernel,
                         cudaFuncAttributeMaxDynamicSharedMemorySize, 224512);

    conv_qkab_kernel<<<512, 256>>>(x, Wq, bq, Wk, bk, Wa, ba, Wb, bb);
    score_kernel<<<dim3(32, 32, 8), 256, 65536>>>();
    stats_kernel<<<BRN * NN, 128>>>();
    out_kernel<<<dim3(32, 8), 256, 224512>>>(Wo, bo, (float*)d_out);
}

// round 2
// speedup vs baseline: 1.3562x; 1.3562x over previous
#include <cuda_runtime.h>

// Problem constants
#define CC   64          // channels
#define NN   4096        // pixels per region (64x64)
#define BRN  8           // B*R = 2*4
#define HW   128

// ---------------- scratch (static __device__ allocations) -------------------
__device__ float g_q[BRN * CC * NN];
__device__ float g_k[BRN * CC * NN];
__device__ float g_a[BRN * CC * NN];
__device__ float g_b[BRN * CC * NN];
__device__ float g_S[(size_t)BRN * NN * NN];   // scores, then P (softmax) in place

// ---------------- packed f32x2 helpers (sm_103a FFMA2) ----------------------
__device__ __forceinline__ unsigned long long pk2(float lo, float hi) {
    unsigned long long r;
    asm("mov.b64 %0, {%1, %2};" : "=l"(r) : "f"(lo), "f"(hi));
    return r;
}
__device__ __forceinline__ void fma2(unsigned long long& d,
                                     unsigned long long a, unsigned long long b) {
    asm("fma.rn.f32x2 %0, %1, %2, %0;" : "+l"(d) : "l"(a), "l"(b));
}
__device__ __forceinline__ float2 upk2(unsigned long long v) {
    float2 r;
    asm("mov.b64 {%0, %1}, %2;" : "=f"(r.x), "=f"(r.y) : "l"(v));
    return r;
}

// Fast exp: FFMA-pipe polynomial (degree-6 exp2 on [-0.5,0.5]); rel err ~1e-7.
__device__ __forceinline__ float fast_exp(float s) {
    float t = s * 1.4426950408889634f;     // log2(e)
    t = fmaxf(t, -125.0f);
    float fl = rintf(t);
    float fr = t - fl;
    float p = 1.5403631e-4f;
    p = fmaf(p, fr, 1.3333558146428443e-3f);
    p = fmaf(p, fr, 9.618129107628477e-3f);
    p = fmaf(p, fr, 5.550410866482158e-2f);
    p = fmaf(p, fr, 2.402265069591007e-1f);
    p = fmaf(p, fr, 6.931471805599453e-1f);
    p = fmaf(p, fr, 1.0f);
    return __int_as_float(((int)fl + 127) << 23) * p;
}

// ============================================================================
// Kernel 1: q,k,a,b = 1x1 convs, written regionized [br][c][n]
// ============================================================================
__global__ __launch_bounds__(256) void conv_qkab_kernel(
    const float* __restrict__ x,
    const float* __restrict__ Wq, const float* __restrict__ bq,
    const float* __restrict__ Wk, const float* __restrict__ bk,
    const float* __restrict__ Wa, const float* __restrict__ ba,
    const float* __restrict__ Wb, const float* __restrict__ bb)
{
    __shared__ float xs[64 * 64];
    int blk   = blockIdx.x;
    int br    = blk >> 6;
    int chunk = blk & 63;
    int b = br >> 2, r = br & 3;
    int n0 = chunk << 6;
    int h  = ((r >> 1) << 6) + chunk;
    int wb = (r & 1) << 6;

    const float* xrow = x + (size_t)(b * CC) * (HW * HW) + (size_t)h * HW + wb;
    for (int idx = threadIdx.x; idx < 64 * 64; idx += 256) {
        int c = idx >> 6, px = idx & 63;
        xs[idx] = xrow[(size_t)c * (HW * HW) + px];
    }
    __syncthreads();

    int px   = threadIdx.x & 63;
    int conv = threadIdx.x >> 6;
    const float *W, *bi;
    float* outp;
    switch (conv) {
        case 0:  W = Wq; bi = bq; outp = g_q; break;
        case 1:  W = Wk; bi = bk; outp = g_k; break;
        case 2:  W = Wa; bi = ba; outp = g_a; break;
        default: W = Wb; bi = bb; outp = g_b; break;
    }

    float acc[64];
    #pragma unroll
    for (int o = 0; o < 64; o++) acc[o] = bi[o];

    for (int c = 0; c < 64; c++) {
        float xv = xs[(c << 6) + px];
        #pragma unroll
        for (int o = 0; o < 64; o++) acc[o] += W[o * 64 + c] * xv;
    }

    size_t base = (size_t)br * CC * NN + n0 + px;
    #pragma unroll
    for (int o = 0; o < 64; o++) outp[base + (size_t)o * NN] = acc[o];
}

// ============================================================================
// Kernel 2: S[br][n][m] = (q . k)/8, FFMA2 register tiles (128x128 block)
// ============================================================================
__global__ __launch_bounds__(256) void score_kernel()
{
    extern __shared__ float sm2[];
    float* qs = sm2;              // [64][128], prescaled by 1/8
    float* ks = sm2 + 64 * 128;   // [64][128]

    int mt = blockIdx.x, nt = blockIdx.y, br = blockIdx.z;
    int m0 = mt << 7, n0 = nt << 7;
    const float* qg = g_q + (size_t)br * CC * NN;
    const float* kg = g_k + (size_t)br * CC * NN;

    for (int idx = threadIdx.x; idx < 64 * 128; idx += 256) {
        int c = idx >> 7, i = idx & 127;
        qs[idx] = qg[(size_t)c * NN + n0 + i] * 0.125f;
        ks[idx] = kg[(size_t)c * NN + m0 + i];
    }
    __syncthreads();

    int ty = threadIdx.x >> 4, tx = threadIdx.x & 15;
    unsigned long long acc[8][4];
    #pragma unroll
    for (int i = 0; i < 8; i++)
        #pragma unroll
        for (int j = 0; j < 4; j++) acc[i][j] = 0ull;

    #pragma unroll 4
    for (int c = 0; c < 64; c++) {
        float4 q0 = *(const float4*)&qs[(c << 7) + (ty << 3)];
        float4 q1 = *(const float4*)&qs[(c << 7) + (ty << 3) + 4];
        const double2* kd = (const double2*)&ks[(c << 7) + (tx << 3)];
        double2 k0 = kd[0], k1 = kd[1];
        unsigned long long kp[4] = {
            (unsigned long long)__double_as_longlong(k0.x),
            (unsigned long long)__double_as_longlong(k0.y),
            (unsigned long long)__double_as_longlong(k1.x),
            (unsigned long long)__double_as_longlong(k1.y)};
        float qv[8] = {q0.x, q0.y, q0.z, q0.w, q1.x, q1.y, q1.z, q1.w};
        #pragma unroll
        for (int i = 0; i < 8; i++) {
            unsigned long long qq = pk2(qv[i], qv[i]);
            #pragma unroll
            for (int mp = 0; mp < 4; mp++) fma2(acc[i][mp], qq, kp[mp]);
        }
    }

    float* Sb = g_S + (size_t)br * NN * NN + (size_t)(n0 + (ty << 3)) * NN
              + m0 + (tx << 3);
    #pragma unroll
    for (int i = 0; i < 8; i++) {
        float2 p0 = upk2(acc[i][0]), p1 = upk2(acc[i][1]);
        float2 p2 = upk2(acc[i][2]), p3 = upk2(acc[i][3]);
        *(float4*)&Sb[(size_t)i * NN]     = make_float4(p0.x, p0.y, p1.x, p1.y);
        *(float4*)&Sb[(size_t)i * NN + 4] = make_float4(p2.x, p2.y, p3.x, p3.y);
    }
}

// ============================================================================
// Kernel 3: fused softmax: P = exp(S - rowmax)/rowsum, in place. 1 block/row.
// ============================================================================
__global__ __launch_bounds__(128) void softmax_kernel()
{
    int row = blockIdx.x;
    float* Srow = g_S + (size_t)row * NN;
    int t = threadIdx.x, lane = t & 31, warp = t >> 5;

    float v[32];
    float mx = -1e30f;
    #pragma unroll
    for (int i = 0; i < 32; i++) {
        v[i] = Srow[t + (i << 7)];
        mx = fmaxf(mx, v[i]);
    }
    #pragma unroll
    for (int off = 16; off; off >>= 1)
        mx = fmaxf(mx, __shfl_xor_sync(0xffffffffu, mx, off));

    __shared__ float red[8];
    if (lane == 0) red[warp] = mx;
    __syncthreads();
    mx = fmaxf(fmaxf(red[0], red[1]), fmaxf(red[2], red[3]));

    float s = 0.f;
    #pragma unroll
    for (int i = 0; i < 32; i++) {
        v[i] = fast_exp(v[i] - mx);
        s += v[i];
    }
    #pragma unroll
    for (int off = 16; off; off >>= 1)
        s += __shfl_xor_sync(0xffffffffu, s, off);
    if (lane == 0) red[4 + warp] = s;
    __syncthreads();
    float rinv = 1.f / (red[4] + red[5] + red[6] + red[7]);

    #pragma unroll
    for (int i = 0; i < 32; i++)
        Srow[t + (i << 7)] = v[i] * rinv;
}

// ============================================================================
// Kernel 4: out[c,m] = sum_j a[c,j]P[j,m] + b[c,j]P[m,j]; fused Wo conv +
//           de-regionize. 64x128 tile, 128 threads, K-chunks of 32, FFMA2.
// ============================================================================
#define PS 132   // padded stride for [KC][128] / [64][128] tiles
#define AS 68    // padded stride for [KC][64] tiles

__global__ __launch_bounds__(128) void out_kernel(
    const float* __restrict__ Wo, const float* __restrict__ bo,
    float* __restrict__ outp)
{
    extern __shared__ float sm4[];
    float* P1s = sm4;               // [32][PS]  P[n0+j][m0+m]
    float* P2t = P1s + 32 * PS;     // [32][PS]  P[m0+i][n0+j] stored [j][i]
    float* aTs = P2t + 32 * PS;     // [32][AS]  a[c][n0+j] stored [j][c]
    float* bTs = aTs + 32 * AS;     // [32][AS]

    int mt = blockIdx.x;            // 0..31
    int br = blockIdx.y;            // 0..7
    int m0 = mt << 7;
    int tid = threadIdx.x;
    int cg = tid >> 4;              // 0..7  -> channels cg*8..+7
    int mg = tid & 15;              // 0..15 -> columns  mg*8..+7

    const float* Pg = g_S + (size_t)br * NN * NN;
    const float* ag = g_a + (size_t)br * CC * NN;
    const float* bg = g_b + (size_t)br * CC * NN;

    unsigned long long acc[8][4];
    #pragma unroll
    for (int i = 0; i < 8; i++)
        #pragma unroll
        for (int j = 0; j < 4; j++) acc[i][j] = 0ull;

    for (int kt = 0; kt < 128; kt++) {
        int n0 = kt << 5;
        __syncthreads();
        // P1: 32 rows x 128 cols, coalesced float4
        #pragma unroll
        for (int it = 0; it < 8; it++) {
            int idx = tid + (it << 7);          // 0..1023
            int j = idx >> 5, f = idx & 31;
            float4 v = *(const float4*)&Pg[(size_t)(n0 + j) * NN + m0 + (f << 2)];
            *(float4*)&P1s[j * PS + (f << 2)] = v;
        }
        // P2: 128 rows x 32 cols -> transposed [j][i]
        #pragma unroll
        for (int it = 0; it < 8; it++) {
            int idx = tid + (it << 7);          // 0..1023
            int i = idx >> 3, f = idx & 7;
            float4 v = *(const float4*)&Pg[(size_t)(m0 + i) * NN + n0 + (f << 2)];
            int j = f << 2;
            P2t[(j + 0) * PS + i] = v.x;
            P2t[(j + 1) * PS + i] = v.y;
            P2t[(j + 2) * PS + i] = v.z;
            P2t[(j + 3) * PS + i] = v.w;
        }
        // a,b: 64 rows x 32 cols -> transposed [j][c]
        #pragma unroll
        for (int it = 0; it < 4; it++) {
            int idx = tid + (it << 7);          // 0..511
            int c = idx >> 3, f = idx & 7;
            int j = f << 2;
            float4 va = *(const float4*)&ag[(size_t)c * NN + n0 + j];
            aTs[(j + 0) * AS + c] = va.x;
            aTs[(j + 1) * AS + c] = va.y;
            aTs[(j + 2) * AS + c] = va.z;
            aTs[(j + 3) * AS + c] = va.w;
            float4 vb = *(const float4*)&bg[(size_t)c * NN + n0 + j];
            bTs[(j + 0) * AS + c] = vb.x;
            bTs[(j + 1) * AS + c] = vb.y;
            bTs[(j + 2) * AS + c] = vb.z;
            bTs[(j + 3) * AS + c] = vb.w;
        }
        __syncthreads();

        #pragma unroll 2
        for (int j = 0; j < 32; j++) {
            const double2* p1d = (const double2*)&P1s[j * PS + (mg << 3)];
            double2 p1a = p1d[0], p1b = p1d[1];
            const double2* p2d = (const double2*)&P2t[j * PS + (mg << 3)];
            double2 p2a = p2d[0], p2b = p2d[1];
            unsigned long long p1p[4] = {
                (unsigned long long)__double_as_longlong(p1a.x),
                (unsigned long long)__double_as_longlong(p1a.y),
                (unsigned long long)__double_as_longlong(p1b.x),
                (unsigned long long)__double_as_longlong(p1b.y)};
            unsigned long long p2p[4] = {
                (unsigned long long)__double_as_longlong(p2a.x),
                (unsigned long long)__double_as_longlong(p2a.y),
                (unsigned long long)__double_as_longlong(p2b.x),
                (unsigned long long)__double_as_longlong(p2b.y)};
            float4 a0 = *(const float4*)&aTs[j * AS + (cg << 3)];
            float4 a1 = *(const float4*)&aTs[j * AS + (cg << 3) + 4];
            float4 b0 = *(const float4*)&bTs[j * AS + (cg << 3)];
            float4 b1 = *(const float4*)&bTs[j * AS + (cg << 3) + 4];
            float av[8] = {a0.x, a0.y, a0.z, a0.w, a1.x, a1.y, a1.z, a1.w};
            float bv[8] = {b0.x, b0.y, b0.z, b0.w, b1.x, b1.y, b1.z, b1.w};
            #pragma unroll
            for (int i = 0; i < 8; i++) {
                unsigned long long aa = pk2(av[i], av[i]);
                unsigned long long bb = pk2(bv[i], bv[i]);
                #pragma unroll
                for (int mp = 0; mp < 4; mp++) {
                    fma2(acc[i][mp], aa, p1p[mp]);
                    fma2(acc[i][mp], bb, p2p[mp]);
                }
            }
        }
    }

    // ---- fused Wo conv + de-regionized store ----
    float* out_s = P1s;             // [64][PS], 64*PS <= 2*32*PS  (exact)
    float* WoT   = aTs;             // [64][AS], 64*AS == 2*32*AS  (exact)
    __syncthreads();
    #pragma unroll
    for (int i = 0; i < 8; i++) {
        #pragma unroll
        for (int mp = 0; mp < 4; mp++) {
            float2 p = upk2(acc[i][mp]);
            out_s[(cg * 8 + i) * PS + (mg << 3) + mp * 2]     = p.x;
            out_s[(cg * 8 + i) * PS + (mg << 3) + mp * 2 + 1] = p.y;
        }
    }
    // WoT[c][o] = Wo[o][c]
    #pragma unroll
    for (int it = 0; it < 8; it++) {
        int idx = tid + (it << 7);          // 0..1023
        int o = idx >> 4, f = idx & 15;
        float4 v = *(const float4*)&Wo[o * 64 + (f << 2)];
        int c = f << 2;
        WoT[(c + 0) * AS + o] = v.x;
        WoT[(c + 1) * AS + o] = v.y;
        WoT[(c + 2) * AS + o] = v.z;
        WoT[(c + 3) * AS + o] = v.w;
    }
    __syncthreads();

    unsigned long long fo[8][4];
    #pragma unroll
    for (int i = 0; i < 8; i++) {
        float bv = bo[cg * 8 + i];
        unsigned long long bp = pk2(bv, bv);
        #pragma unroll
        for (int mp = 0; mp < 4; mp++) fo[i][mp] = bp;
    }
    #pragma unroll 4
    for (int c = 0; c < 64; c++) {
        float4 w0 = *(const float4*)&WoT[c * AS + (cg << 3)];
        float4 w1 = *(const float4*)&WoT[c * AS + (cg << 3) + 4];
        float wv[8] = {w0.x, w0.y, w0.z, w0.w, w1.x, w1.y, w1.z, w1.w};
        const double2* od = (const double2*)&out_s[c * PS + (mg << 3)];
        double2 oa = od[0], ob = od[1];
        unsigned long long op[4] = {
            (unsigned long long)__double_as_longlong(oa.x),
            (unsigned long long)__double_as_longlong(oa.y),
            (unsigned long long)__double_as_longlong(ob.x),
            (unsigned long long)__double_as_longlong(ob.y)};
        #pragma unroll
        for (int i = 0; i < 8; i++) {
            unsigned long long ww = pk2(wv[i], wv[i]);
            #pragma unroll
            for (int mp = 0; mp < 4; mp++) fma2(fo[i][mp], ww, op[mp]);
        }
    }

    int b = br >> 2, r = br & 3;
    int nbase = m0 + (mg << 3);
    int h = ((r >> 1) << 6) + (nbase >> 6);
    int w = ((r & 1) << 6) + (nbase & 63);
    #pragma unroll
    for (int i = 0; i < 8; i++) {
        int o = cg * 8 + i;
        float2 f0 = upk2(fo[i][0]), f1 = upk2(fo[i][1]);
        float2 f2 = upk2(fo[i][2]), f3 = upk2(fo[i][3]);
        float* dst = outp + (((size_t)(b * 64 + o)) << 14) + (h << 7) + w;
        *(float4*)dst       = make_float4(f0.x, f0.y, f1.x, f1.y);
        *(float4*)(dst + 4) = make_float4(f2.x, f2.y, f3.x, f3.y);
    }
}

// ============================================================================
extern "C" void kernel_launch(void* const* d_in, const int* in_sizes, int n_in,
                              void* d_out, int out_size)
{
    const float* x  = (const float*)d_in[0];
    const float* Wq = (const float*)d_in[1];
    const float* bq = (const float*)d_in[2];
    const float* Wk = (const float*)d_in[3];
    const float* bk = (const float*)d_in[4];
    const float* Wa = (const float*)d_in[5];
    const float* ba = (const float*)d_in[6];
    const float* Wb = (const float*)d_in[7];
    const float* bb = (const float*)d_in[8];
    const float* Wo = (const float*)d_in[9];
    const float* bo = (const float*)d_in[10];

    cudaFuncSetAttribute(score_kernel,
                         cudaFuncAttributeMaxDynamicSharedMemorySize, 65536);
    cudaFuncSetAttribute(out_kernel,
                         cudaFuncAttributeMaxDynamicSharedMemorySize, 51200);

    conv_qkab_kernel<<<512, 256>>>(x, Wq, bq, Wk, bk, Wa, ba, Wb, bb);
    score_kernel<<<dim3(32, 32, 8), 256, 65536>>>();
    softmax_kernel<<<BRN * NN, 128>>>();
    out_kernel<<<dim3(32, 8), 128, 51200>>>(Wo, bo, (float*)d_out);
}

// round 3
// speedup vs baseline: 2.0810x; 1.5345x over previous
#include <cuda_runtime.h>

// Problem constants
#define CC   64          // channels
#define NN   4096        // pixels per region (64x64)
#define BRN  8           // B*R = 2*4
#define HW   128

// ---------------- scratch (static __device__ allocations) -------------------
__device__ float g_q[BRN * CC * NN];
__device__ float g_k[BRN * CC * NN];
__device__ float g_a[BRN * CC * NN];
__device__ float g_b[BRN * CC * NN];
__device__ float g_S[(size_t)BRN * NN * NN];   // scores, then P (softmax) in place

// ---------------- packed f32x2 helpers (sm_103a FFMA2) ----------------------
__device__ __forceinline__ unsigned long long pk2(float lo, float hi) {
    unsigned long long r;
    asm("mov.b64 %0, {%1, %2};" : "=l"(r) : "f"(lo), "f"(hi));
    return r;
}
__device__ __forceinline__ void fma2(unsigned long long& d,
                                     unsigned long long a, unsigned long long b) {
    asm("fma.rn.f32x2 %0, %1, %2, %0;" : "+l"(d) : "l"(a), "l"(b));
}
__device__ __forceinline__ float2 upk2(unsigned long long v) {
    float2 r;
    asm("mov.b64 {%0, %1}, %2;" : "=f"(r.x), "=f"(r.y) : "l"(v));
    return r;
}

// Fast exp: FFMA-pipe polynomial (degree-6 exp2 on [-0.5,0.5]); rel err ~1e-7.
__device__ __forceinline__ float fast_exp(float s) {
    float t = s * 1.4426950408889634f;     // log2(e)
    t = fmaxf(t, -125.0f);
    float fl = rintf(t);
    float fr = t - fl;
    float p = 1.5403631e-4f;
    p = fmaf(p, fr, 1.3333558146428443e-3f);
    p = fmaf(p, fr, 9.618129107628477e-3f);
    p = fmaf(p, fr, 5.550410866482158e-2f);
    p = fmaf(p, fr, 2.402265069591007e-1f);
    p = fmaf(p, fr, 6.931471805599453e-1f);
    p = fmaf(p, fr, 1.0f);
    return __int_as_float(((int)fl + 127) << 23) * p;
}

// ============================================================================
// Kernel 1: q,k,a,b = 1x1 convs, written regionized [br][c][n]
// ============================================================================
__global__ __launch_bounds__(256) void conv_qkab_kernel(
    const float* __restrict__ x,
    const float* __restrict__ Wq, const float* __restrict__ bq,
    const float* __restrict__ Wk, const float* __restrict__ bk,
    const float* __restrict__ Wa, const float* __restrict__ ba,
    const float* __restrict__ Wb, const float* __restrict__ bb)
{
    __shared__ float xs[64 * 64];
    int blk   = blockIdx.x;
    int br    = blk >> 6;
    int chunk = blk & 63;
    int b = br >> 2, r = br & 3;
    int n0 = chunk << 6;
    int h  = ((r >> 1) << 6) + chunk;
    int wb = (r & 1) << 6;

    const float* xrow = x + (size_t)(b * CC) * (HW * HW) + (size_t)h * HW + wb;
    for (int idx = threadIdx.x; idx < 64 * 64; idx += 256) {
        int c = idx >> 6, px = idx & 63;
        xs[idx] = xrow[(size_t)c * (HW * HW) + px];
    }
    __syncthreads();

    int px   = threadIdx.x & 63;
    int conv = threadIdx.x >> 6;
    const float *W, *bi;
    float* outp;
    switch (conv) {
        case 0:  W = Wq; bi = bq; outp = g_q; break;
        case 1:  W = Wk; bi = bk; outp = g_k; break;
        case 2:  W = Wa; bi = ba; outp = g_a; break;
        default: W = Wb; bi = bb; outp = g_b; break;
    }

    float acc[64];
    #pragma unroll
    for (int o = 0; o < 64; o++) acc[o] = bi[o];

    for (int c = 0; c < 64; c++) {
        float xv = xs[(c << 6) + px];
        #pragma unroll
        for (int o = 0; o < 64; o++) acc[o] += W[o * 64 + c] * xv;
    }

    size_t base = (size_t)br * CC * NN + n0 + px;
    #pragma unroll
    for (int o = 0; o < 64; o++) outp[base + (size_t)o * NN] = acc[o];
}

// ============================================================================
// Kernel 2: S[br][n][m] = (q . k)/8, FFMA2 register tiles (128x128 block)
// ============================================================================
__global__ __launch_bounds__(256) void score_kernel()
{
    extern __shared__ float sm2[];
    float* qs = sm2;              // [64][128], prescaled by 1/8
    float* ks = sm2 + 64 * 128;   // [64][128]

    int mt = blockIdx.x, nt = blockIdx.y, br = blockIdx.z;
    int m0 = mt << 7, n0 = nt << 7;
    const float* qg = g_q + (size_t)br * CC * NN;
    const float* kg = g_k + (size_t)br * CC * NN;

    for (int idx = threadIdx.x; idx < 64 * 128; idx += 256) {
        int c = idx >> 7, i = idx & 127;
        qs[idx] = qg[(size_t)c * NN + n0 + i] * 0.125f;
        ks[idx] = kg[(size_t)c * NN + m0 + i];
    }
    __syncthreads();

    int ty = threadIdx.x >> 4, tx = threadIdx.x & 15;
    unsigned long long acc[8][4];
    #pragma unroll
    for (int i = 0; i < 8; i++)
        #pragma unroll
        for (int j = 0; j < 4; j++) acc[i][j] = 0ull;

    #pragma unroll 4
    for (int c = 0; c < 64; c++) {
        float4 q0 = *(const float4*)&qs[(c << 7) + (ty << 3)];
        float4 q1 = *(const float4*)&qs[(c << 7) + (ty << 3) + 4];
        const double2* kd = (const double2*)&ks[(c << 7) + (tx << 3)];
        double2 k0 = kd[0], k1 = kd[1];
        unsigned long long kp[4] = {
            (unsigned long long)__double_as_longlong(k0.x),
            (unsigned long long)__double_as_longlong(k0.y),
            (unsigned long long)__double_as_longlong(k1.x),
            (unsigned long long)__double_as_longlong(k1.y)};
        float qv[8] = {q0.x, q0.y, q0.z, q0.w, q1.x, q1.y, q1.z, q1.w};
        #pragma unroll
        for (int i = 0; i < 8; i++) {
            unsigned long long qq = pk2(qv[i], qv[i]);
            #pragma unroll
            for (int mp = 0; mp < 4; mp++) fma2(acc[i][mp], qq, kp[mp]);
        }
    }

    float* Sb = g_S + (size_t)br * NN * NN + (size_t)(n0 + (ty << 3)) * NN
              + m0 + (tx << 3);
    #pragma unroll
    for (int i = 0; i < 8; i++) {
        float2 p0 = upk2(acc[i][0]), p1 = upk2(acc[i][1]);
        float2 p2 = upk2(acc[i][2]), p3 = upk2(acc[i][3]);
        *(float4*)&Sb[(size_t)i * NN]     = make_float4(p0.x, p0.y, p1.x, p1.y);
        *(float4*)&Sb[(size_t)i * NN + 4] = make_float4(p2.x, p2.y, p3.x, p3.y);
    }
}

// ============================================================================
// Kernel 3: fused softmax: P = exp(S - rowmax)/rowsum, in place. 1 block/row.
// ============================================================================
__global__ __launch_bounds__(128) void softmax_kernel()
{
    int row = blockIdx.x;
    float* Srow = g_S + (size_t)row * NN;
    int t = threadIdx.x, lane = t & 31, warp = t >> 5;

    float v[32];
    float mx = -1e30f;
    #pragma unroll
    for (int i = 0; i < 32; i++) {
        v[i] = Srow[t + (i << 7)];
        mx = fmaxf(mx, v[i]);
    }
    #pragma unroll
    for (int off = 16; off; off >>= 1)
        mx = fmaxf(mx, __shfl_xor_sync(0xffffffffu, mx, off));

    __shared__ float red[8];
    if (lane == 0) red[warp] = mx;
    __syncthreads();
    mx = fmaxf(fmaxf(red[0], red[1]), fmaxf(red[2], red[3]));

    float s = 0.f;
    #pragma unroll
    for (int i = 0; i < 32; i++) {
        v[i] = fast_exp(v[i] - mx);
        s += v[i];
    }
    #pragma unroll
    for (int off = 16; off; off >>= 1)
        s += __shfl_xor_sync(0xffffffffu, s, off);
    if (lane == 0) red[4 + warp] = s;
    __syncthreads();
    float rinv = 1.f / (red[4] + red[5] + red[6] + red[7]);

    #pragma unroll
    for (int i = 0; i < 32; i++)
        Srow[t + (i << 7)] = v[i] * rinv;
}

// ============================================================================
// Kernel 4: out[c,m] = sum_j a[c,j]P[j,m] + b[c,j]P[m,j]; fused Wo conv +
//           de-regionize. 64x128 tile, 128 threads, K-chunks of 32, FFMA2.
// ============================================================================
#define PS 132   // padded stride for [KC][128] / [64][128] tiles
#define AS 68    // padded stride for [KC][64] tiles

__global__ __launch_bounds__(128) void out_kernel(
    const float* __restrict__ Wo, const float* __restrict__ bo,
    float* __restrict__ outp)
{
    extern __shared__ float sm4[];
    float* P1s = sm4;               // [32][PS]  P[n0+j][m0+m]
    float* P2t = P1s + 32 * PS;     // [32][PS]  P[m0+i][n0+j] stored [j][i]
    float* aTs = P2t + 32 * PS;     // [32][AS]  a[c][n0+j] stored [j][c]
    float* bTs = aTs + 32 * AS;     // [32][AS]

    int mt = blockIdx.x;            // 0..31
    int br = blockIdx.y;            // 0..7
    int m0 = mt << 7;
    int tid = threadIdx.x;
    int cg = tid >> 4;              // 0..7  -> channels cg*8..+7
    int mg = tid & 15;              // 0..15 -> columns  mg*8..+7

    const float* Pg = g_S + (size_t)br * NN * NN;
    const float* ag = g_a + (size_t)br * CC * NN;
    const float* bg = g_b + (size_t)br * CC * NN;

    unsigned long long acc[8][4];
    #pragma unroll
    for (int i = 0; i < 8; i++)
        #pragma unroll
        for (int j = 0; j < 4; j++) acc[i][j] = 0ull;

    for (int kt = 0; kt < 128; kt++) {
        int n0 = kt << 5;
        __syncthreads();
        // P1: 32 rows x 128 cols, coalesced float4
        #pragma unroll
        for (int it = 0; it < 8; it++) {
            int idx = tid + (it << 7);          // 0..1023
            int j = idx >> 5, f = idx & 31;
            float4 v = *(const float4*)&Pg[(size_t)(n0 + j) * NN + m0 + (f << 2)];
            *(float4*)&P1s[j * PS + (f << 2)] = v;
        }
        // P2: 128 rows x 32 cols -> transposed [j][i]
        #pragma unroll
        for (int it = 0; it < 8; it++) {
            int idx = tid + (it << 7);          // 0..1023
            int i = idx >> 3, f = idx & 7;
            float4 v = *(const float4*)&Pg[(size_t)(m0 + i) * NN + n0 + (f << 2)];
            int j = f << 2;
            P2t[(j + 0) * PS + i] = v.x;
            P2t[(j + 1) * PS + i] = v.y;
            P2t[(j + 2) * PS + i] = v.z;
            P2t[(j + 3) * PS + i] = v.w;
        }
        // a,b: 64 rows x 32 cols -> transposed [j][c]
        #pragma unroll
        for (int it = 0; it < 4; it++) {
            int idx = tid + (it << 7);          // 0..511
            int c = idx >> 3, f = idx & 7;
            int j = f << 2;
            float4 va = *(const float4*)&ag[(size_t)c * NN + n0 + j];
            aTs[(j + 0) * AS + c] = va.x;
            aTs[(j + 1) * AS + c] = va.y;
            aTs[(j + 2) * AS + c] = va.z;
            aTs[(j + 3) * AS + c] = va.w;
            float4 vb = *(const float4*)&bg[(size_t)c * NN + n0 + j];
            bTs[(j + 0) * AS + c] = vb.x;
            bTs[(j + 1) * AS + c] = vb.y;
            bTs[(j + 2) * AS + c] = vb.z;
            bTs[(j + 3) * AS + c] = vb.w;
        }
        __syncthreads();

        #pragma unroll 2
        for (int j = 0; j < 32; j++) {
            const double2* p1d = (const double2*)&P1s[j * PS + (mg << 3)];
            double2 p1a = p1d[0], p1b = p1d[1];
            const double2* p2d = (const double2*)&P2t[j * PS + (mg << 3)];
            double2 p2a = p2d[0], p2b = p2d[1];
            unsigned long long p1p[4] = {
                (unsigned long long)__double_as_longlong(p1a.x),
                (unsigned long long)__double_as_longlong(p1a.y),
                (unsigned long long)__double_as_longlong(p1b.x),
                (unsigned long long)__double_as_longlong(p1b.y)};
            unsigned long long p2p[4] = {
                (unsigned long long)__double_as_longlong(p2a.x),
                (unsigned long long)__double_as_longlong(p2a.y),
                (unsigned long long)__double_as_longlong(p2b.x),
                (unsigned long long)__double_as_longlong(p2b.y)};
            float4 a0 = *(const float4*)&aTs[j * AS + (cg << 3)];
            float4 a1 = *(const float4*)&aTs[j * AS + (cg << 3) + 4];
            float4 b0 = *(const float4*)&bTs[j * AS + (cg << 3)];
            float4 b1 = *(const float4*)&bTs[j * AS + (cg << 3) + 4];
            float av[8] = {a0.x, a0.y, a0.z, a0.w, a1.x, a1.y, a1.z, a1.w};
            float bv[8] = {b0.x, b0.y, b0.z, b0.w, b1.x, b1.y, b1.z, b1.w};
            #pragma unroll
            for (int i = 0; i < 8; i++) {
                unsigned long long aa = pk2(av[i], av[i]);
                unsigned long long bb = pk2(bv[i], bv[i]);
                #pragma unroll
                for (int mp = 0; mp < 4; mp++) {
                    fma2(acc[i][mp], aa, p1p[mp]);
                    fma2(acc[i][mp], bb, p2p[mp]);
                }
            }
        }
    }

    // ---- fused Wo conv + de-regionized store ----
    float* out_s = P1s;             // [64][PS], 64*PS <= 2*32*PS  (exact)
    float* WoT   = aTs;             // [64][AS], 64*AS == 2*32*AS  (exact)
    __syncthreads();
    #pragma unroll
    for (int i = 0; i < 8; i++) {
        #pragma unroll
        for (int mp = 0; mp < 4; mp++) {
            float2 p = upk2(acc[i][mp]);
            out_s[(cg * 8 + i) * PS + (mg << 3) + mp * 2]     = p.x;
            out_s[(cg * 8 + i) * PS + (mg << 3) + mp * 2 + 1] = p.y;
        }
    }
    // WoT[c][o] = Wo[o][c]
    #pragma unroll
    for (int it = 0; it < 8; it++) {
        int idx = tid + (it << 7);          // 0..1023
        int o = idx >> 4, f = idx & 15;
        float4 v = *(const float4*)&Wo[o * 64 + (f << 2)];
        int c = f << 2;
        WoT[(c + 0) * AS + o] = v.x;
        WoT[(c + 1) * AS + o] = v.y;
        WoT[(c + 2) * AS + o] = v.z;
        WoT[(c + 3) * AS + o] = v.w;
    }
    __syncthreads();

    unsigned long long fo[8][4];
    #pragma unroll
    for (int i = 0; i < 8; i++) {
        float bv = bo[cg * 8 + i];
        unsigned long long bp = pk2(bv, bv);
        #pragma unroll
        for (int mp = 0; mp < 4; mp++) fo[i][mp] = bp;
    }
    #pragma unroll 4
    for (int c = 0; c < 64; c++) {
        float4 w0 = *(const float4*)&WoT[c * AS + (cg << 3)];
        float4 w1 = *(const float4*)&WoT[c * AS + (cg << 3) + 4];
        float wv[8] = {w0.x, w0.y, w0.z, w0.w, w1.x, w1.y, w1.z, w1.w};
        const double2* od = (const double2*)&out_s[c * PS + (mg << 3)];
        double2 oa = od[0], ob = od[1];
        unsigned long long op[4] = {
            (unsigned long long)__double_as_longlong(oa.x),
            (unsigned long long)__double_as_longlong(oa.y),
            (unsigned long long)__double_as_longlong(ob.x),
            (unsigned long long)__double_as_longlong(ob.y)};
        #pragma unroll
        for (int i = 0; i < 8; i++) {
            unsigned long long ww = pk2(wv[i], wv[i]);
            #pragma unroll
            for (int mp = 0; mp < 4; mp++) fma2(fo[i][mp], ww, op[mp]);
        }
    }

    int b = br >> 2, r = br & 3;
    int nbase = m0 + (mg << 3);
    int h = ((r >> 1) << 6) + (nbase >> 6);
    int w = ((r & 1) << 6) + (nbase & 63);
    #pragma unroll
    for (int i = 0; i < 8; i++) {
        int o = cg * 8 + i;
        float2 f0 = upk2(fo[i][0]), f1 = upk2(fo[i][1]);
        float2 f2 = upk2(fo[i][2]), f3 = upk2(fo[i][3]);
        float* dst = outp + (((size_t)(b * 64 + o)) << 14) + (h << 7) + w;
        *(float4*)dst       = make_float4(f0.x, f0.y, f1.x, f1.y);
        *(float4*)(dst + 4) = make_float4(f2.x, f2.y, f3.x, f3.y);
    }
}

// ============================================================================
extern "C" void kernel_launch(void* const* d_in, const int* in_sizes, int n_in,
                              void* d_out, int out_size)
{
    const float* x  = (const float*)d_in[0];
    const float* Wq = (const float*)d_in[1];
    const float* bq = (const float*)d_in[2];
    const float* Wk = (const float*)d_in[3];
    const float* bk = (const float*)d_in[4];
    const float* Wa = (const float*)d_in[5];
    const float* ba = (const float*)d_in[6];
    const float* Wb = (const float*)d_in[7];
    const float* bb = (const float*)d_in[8];
    const float* Wo = (const float*)d_in[9];
    const float* bo = (const float*)d_in[10];

    cudaFuncSetAttribute(score_kernel,
                         cudaFuncAttributeMaxDynamicSharedMemorySize, 65536);
    cudaFuncSetAttribute(out_kernel,
                         cudaFuncAttributeMaxDynamicSharedMemorySize, 51200);

    conv_qkab_kernel<<<512, 256>>>(x, Wq, bq, Wk, bk, Wa, ba, Wb, bb);
    score_kernel<<<dim3(32, 32, 8), 256, 65536>>>();
    softmax_kernel<<<BRN * NN, 128>>>();
    out_kernel<<<dim3(32, 8), 128, 51200>>>(Wo, bo, (float*)d_out);
}

// round 4
// speedup vs baseline: 3.4613x; 1.6633x over previous
#include <cuda_runtime.h>
#include <cuda_bf16.h>

#define CC   64
#define NN   4096
#define BRN  8
#define HW   128

// ---------------- scratch ----------------
__device__ __nv_bfloat16 g_qh[BRN * NN * CC];   // q/8, layout [br][n][c]
__device__ __nv_bfloat16 g_ql[BRN * NN * CC];
__device__ __nv_bfloat16 g_kh[BRN * NN * CC];   // k,   layout [br][m][c]
__device__ __nv_bfloat16 g_kl[BRN * NN * CC];
__device__ float g_a[BRN * CC * NN];            // a' = (Wo Wa)x + Wo ba, [br][c][n]
__device__ float g_b[BRN * CC * NN];            // b'
__device__ __nv_bfloat16 g_Ph[(size_t)BRN * NN * NN];  // e = exp(S), hi plane
__device__ __nv_bfloat16 g_Pl[(size_t)BRN * NN * NN];  // lo plane
__device__ float g_psum[BRN * NN * 32];         // partial row sums
__device__ float g_rinv[BRN * NN];
__device__ float g_W2a[CC * CC], g_W2b[CC * CC], g_b2a[CC], g_b2b[CC];

// ---------------- helpers ----------------
__device__ __forceinline__ unsigned sptr(const void* p) {
    return (unsigned)__cvta_generic_to_shared(p);
}
__device__ __forceinline__ void ldsm4(unsigned* r, unsigned a) {
    asm volatile("ldmatrix.sync.aligned.m8n8.x4.shared.b16 {%0,%1,%2,%3},[%4];"
                 : "=r"(r[0]), "=r"(r[1]), "=r"(r[2]), "=r"(r[3]) : "r"(a));
}
__device__ __forceinline__ void ldsm4t(unsigned* r, unsigned a) {
    asm volatile("ldmatrix.sync.aligned.m8n8.x4.trans.shared.b16 {%0,%1,%2,%3},[%4];"
                 : "=r"(r[0]), "=r"(r[1]), "=r"(r[2]), "=r"(r[3]) : "r"(a));
}
__device__ __forceinline__ void mma_bf16(float* d, const unsigned* a,
                                         unsigned b0, unsigned b1) {
    asm volatile("mma.sync.aligned.m16n8k16.row.col.f32.bf16.bf16.f32 "
                 "{%0,%1,%2,%3},{%4,%5,%6,%7},{%8,%9},{%0,%1,%2,%3};"
                 : "+f"(d[0]), "+f"(d[1]), "+f"(d[2]), "+f"(d[3])
                 : "r"(a[0]), "r"(a[1]), "r"(a[2]), "r"(a[3]), "r"(b0), "r"(b1));
}
__device__ __forceinline__ float fast_exp(float s) {
    float t = s * 1.4426950408889634f;
    t = fmaxf(t, -125.0f);
    float fl = rintf(t);
    float fr = t - fl;
    float p = 1.5403631e-4f;
    p = fmaf(p, fr, 1.3333558146428443e-3f);
    p = fmaf(p, fr, 9.618129107628477e-3f);
    p = fmaf(p, fr, 5.550410866482158e-2f);
    p = fmaf(p, fr, 2.402265069591007e-1f);
    p = fmaf(p, fr, 6.931471805599453e-1f);
    p = fmaf(p, fr, 1.0f);
    return __int_as_float(((int)fl + 127) << 23) * p;
}
// split float4 into hi/lo bf16 quads, store at dst (aligned 8B)
__device__ __forceinline__ void split_store4(float4 v, __nv_bfloat16* dh,
                                             __nv_bfloat16* dl) {
    __nv_bfloat162 h01 = __float22bfloat162_rn(make_float2(v.x, v.y));
    __nv_bfloat162 h23 = __float22bfloat162_rn(make_float2(v.z, v.w));
    __nv_bfloat162 l01 = __float22bfloat162_rn(make_float2(
        v.x - __bfloat162float(h01.x), v.y - __bfloat162float(h01.y)));
    __nv_bfloat162 l23 = __float22bfloat162_rn(make_float2(
        v.z - __bfloat162float(h23.x), v.w - __bfloat162float(h23.y)));
    *(__nv_bfloat162*)(dh)     = h01;
    *(__nv_bfloat162*)(dh + 2) = h23;
    *(__nv_bfloat162*)(dl)     = l01;
    *(__nv_bfloat162*)(dl + 2) = l23;
}

// ============================================================================
// Kernel 0: combined weights  W2a = Wo@Wa, b2a = Wo@ba (likewise b)
// ============================================================================
__global__ __launch_bounds__(256) void combine_w_kernel(
    const float* __restrict__ Wo,
    const float* __restrict__ Wa, const float* __restrict__ ba,
    const float* __restrict__ Wb, const float* __restrict__ bb)
{
    __shared__ float so[4096], sa[4096], sb[4096];
    int t = threadIdx.x;
    for (int i = t; i < 4096; i += 256) { so[i] = Wo[i]; sa[i] = Wa[i]; sb[i] = Wb[i]; }
    __syncthreads();
    for (int e = t; e < 4096; e += 256) {
        int o = e >> 6, c = e & 63;
        float s1 = 0.f, s2 = 0.f;
        for (int k = 0; k < 64; k++) {
            s1 += so[o * 64 + k] * sa[k * 64 + c];
            s2 += so[o * 64 + k] * sb[k * 64 + c];
        }
        g_W2a[e] = s1; g_W2b[e] = s2;
    }
    if (t < 64) {
        float s1 = 0.f, s2 = 0.f;
        for (int k = 0; k < 64; k++) {
            s1 += so[t * 64 + k] * ba[k];
            s2 += so[t * 64 + k] * bb[k];
        }
        g_b2a[t] = s1; g_b2b[t] = s2;
    }
}

// ============================================================================
// Kernel 1: 1x1 convs -> q/8,k bf16 planes [br][n][c]; a',b' fp32 [br][c][n]
// ============================================================================
__global__ __launch_bounds__(256) void conv_kernel(
    const float* __restrict__ x,
    const float* __restrict__ Wq, const float* __restrict__ bq,
    const float* __restrict__ Wk, const float* __restrict__ bk)
{
    __shared__ float xs[64 * 64];
    int blk = blockIdx.x;
    int br = blk >> 6, chunk = blk & 63;
    int b = br >> 2, r = br & 3;
    int n0 = chunk << 6;
    int h = ((r >> 1) << 6) + chunk;
    int wb = (r & 1) << 6;

    const float* xrow = x + (size_t)(b * CC) * (HW * HW) + (size_t)h * HW + wb;
    for (int idx = threadIdx.x; idx < 64 * 64; idx += 256) {
        int c = idx >> 6, px = idx & 63;
        xs[idx] = xrow[(size_t)c * (HW * HW) + px];
    }
    __syncthreads();

    int px = threadIdx.x & 63;
    int conv = threadIdx.x >> 6;
    const float *W, *bi;
    if      (conv == 0) { W = Wq;    bi = bq;    }
    else if (conv == 1) { W = Wk;    bi = bk;    }
    else if (conv == 2) { W = g_W2a; bi = g_b2a; }
    else                { W = g_W2b; bi = g_b2b; }

    float acc[64];
    #pragma unroll
    for (int o = 0; o < 64; o++) acc[o] = bi[o];
    for (int c = 0; c < 64; c++) {
        float xv = xs[(c << 6) + px];
        #pragma unroll
        for (int o = 0; o < 64; o++) acc[o] += W[o * 64 + c] * xv;
    }

    if (conv < 2) {
        float sc = (conv == 0) ? 0.125f : 1.0f;
        __nv_bfloat16* ph = (conv == 0 ? g_qh : g_kh);
        __nv_bfloat16* pl = (conv == 0 ? g_ql : g_kl);
        size_t row = ((size_t)br * NN + n0 + px) * 64;
        #pragma unroll
        for (int o = 0; o < 64; o += 4) {
            float4 v = make_float4(acc[o] * sc, acc[o+1] * sc,
                                   acc[o+2] * sc, acc[o+3] * sc);
            split_store4(v, ph + row + o, pl + row + o);
        }
    } else {
        float* outp = (conv == 2 ? g_a : g_b);
        size_t base = (size_t)br * CC * NN + n0 + px;
        #pragma unroll
        for (int o = 0; o < 64; o++) outp[base + (size_t)o * NN] = acc[o];
    }
}

// ============================================================================
// Kernel 2: e = exp(q.k) via HMMA; 128n x 128m tile; writes Ph/Pl + psums.
// ============================================================================
#define QS 72
__global__ __launch_bounds__(256, 1) void score_kernel()
{
    extern __shared__ __nv_bfloat16 smq[];
    __nv_bfloat16* QH = smq;
    __nv_bfloat16* QL = QH + 128 * QS;
    __nv_bfloat16* KH = QL + 128 * QS;
    __nv_bfloat16* KL = KH + 128 * QS;
    __shared__ float pr2[8][64];

    int mt = blockIdx.x, nt = blockIdx.y, brr = blockIdx.z;
    int n0 = nt << 7, m0 = mt << 7;
    int t = threadIdx.x, lane = t & 31, w = t >> 5;
    int wn = (w >> 2) << 6, wm = (w & 3) << 5;

    for (int i = t; i < 512; i += 256) ((float*)pr2)[i] = 0.f;

    {
        const __nv_bfloat16* srcs[4] = {g_qh, g_ql, g_kh, g_kl};
        __nv_bfloat16* dsts[4] = {QH, QL, KH, KL};
        #pragma unroll
        for (int pl = 0; pl < 4; pl++) {
            int rb = (pl < 2) ? n0 : m0;
            const __nv_bfloat16* s = srcs[pl];
            __nv_bfloat16* d = dsts[pl];
            #pragma unroll
            for (int it = 0; it < 4; it++) {
                int idx = t + (it << 8);
                int row = idx >> 3, f = idx & 7;
                *(uint4*)(d + row * QS + (f << 3)) =
                    *((const uint4*)(s + ((size_t)brr * NN + rb + row) * 64) + f);
            }
        }
    }
    __syncthreads();

    float acc[4][4][4];
    #pragma unroll
    for (int i = 0; i < 4; i++)
        #pragma unroll
        for (int j = 0; j < 4; j++)
            #pragma unroll
            for (int k = 0; k < 4; k++) acc[i][j][k] = 0.f;

    int arow = wn + (lane & 15);
    int brow = wm + (lane & 7) + ((lane >> 4) << 3);
    #pragma unroll
    for (int kk = 0; kk < 4; kk++) {
        int acol = (kk << 4) + ((lane >> 4) << 3);
        int bcol = (kk << 4) + (lane & 8);
        unsigned qh[4][4], ql[4][4], kh[4][2], kl[4][2];
        #pragma unroll
        for (int mi = 0; mi < 4; mi++) {
            ldsm4(qh[mi], sptr(QH + (arow + mi * 16) * QS + acol));
            ldsm4(ql[mi], sptr(QL + (arow + mi * 16) * QS + acol));
        }
        #pragma unroll
        for (int nb = 0; nb < 2; nb++) {
            unsigned r[4];
            ldsm4(r, sptr(KH + (brow + nb * 16) * QS + bcol));
            kh[nb*2][0]=r[0]; kh[nb*2][1]=r[1]; kh[nb*2+1][0]=r[2]; kh[nb*2+1][1]=r[3];
            ldsm4(r, sptr(KL + (brow + nb * 16) * QS + bcol));
            kl[nb*2][0]=r[0]; kl[nb*2][1]=r[1]; kl[nb*2+1][0]=r[2]; kl[nb*2+1][1]=r[3];
        }
        #pragma unroll
        for (int mi = 0; mi < 4; mi++)
            #pragma unroll
            for (int ni = 0; ni < 4; ni++) {
                mma_bf16(acc[mi][ni], qh[mi], kh[ni][0], kh[ni][1]);
                mma_bf16(acc[mi][ni], ql[mi], kh[ni][0], kh[ni][1]);
                mma_bf16(acc[mi][ni], qh[mi], kl[ni][0], kl[ni][1]);
            }
    }

    // exp + split-store + deterministic per-warp row partials
    size_t Pbase = (size_t)brr * NN * NN;
    int rloc = lane >> 2;              // 0..7
    int cloc = (lane & 3) << 1;        // 0,2,4,6
    #pragma unroll
    for (int mi = 0; mi < 4; mi++) {
        float s0 = 0.f, s1 = 0.f;
        #pragma unroll
        for (int ni = 0; ni < 4; ni++) {
            float e0 = fast_exp(acc[mi][ni][0]);
            float e1 = fast_exp(acc[mi][ni][1]);
            float e2 = fast_exp(acc[mi][ni][2]);
            float e3 = fast_exp(acc[mi][ni][3]);
            s0 += e0 + e1; s1 += e2 + e3;
            int row0 = n0 + wn + mi * 16 + rloc;
            int col  = m0 + wm + ni * 8 + cloc;
            __nv_bfloat162 h01 = __float22bfloat162_rn(make_float2(e0, e1));
            __nv_bfloat162 l01 = __float22bfloat162_rn(make_float2(
                e0 - __bfloat162float(h01.x), e1 - __bfloat162float(h01.y)));
            __nv_bfloat162 h23 = __float22bfloat162_rn(make_float2(e2, e3));
            __nv_bfloat162 l23 = __float22bfloat162_rn(make_float2(
                e2 - __bfloat162float(h23.x), e3 - __bfloat162float(h23.y)));
            *(__nv_bfloat162*)(g_Ph + Pbase + (size_t)row0 * NN + col)       = h01;
            *(__nv_bfloat162*)(g_Pl + Pbase + (size_t)row0 * NN + col)       = l01;
            *(__nv_bfloat162*)(g_Ph + Pbase + (size_t)(row0 + 8) * NN + col) = h23;
            *(__nv_bfloat162*)(g_Pl + Pbase + (size_t)(row0 + 8) * NN + col) = l23;
        }
        s0 += __shfl_xor_sync(0xffffffffu, s0, 1);
        s0 += __shfl_xor_sync(0xffffffffu, s0, 2);
        s1 += __shfl_xor_sync(0xffffffffu, s1, 1);
        s1 += __shfl_xor_sync(0xffffffffu, s1, 2);
        if ((lane & 3) == 0) {
            pr2[w][mi * 16 + rloc]     = pr2[w][mi * 16 + rloc] + s0;
            pr2[w][mi * 16 + rloc + 8] = pr2[w][mi * 16 + rloc + 8] + s1;
        }
    }
    __syncthreads();
    if (t < 128) {
        int g4 = (t >> 6) << 2, lr = t & 63;
        float s = pr2[g4][lr] + pr2[g4+1][lr] + pr2[g4+2][lr] + pr2[g4+3][lr];
        g_psum[((size_t)brr * NN + n0 + t) * 32 + mt] = s;
    }
}

// ============================================================================
// Kernel 3: rinv[row] = 1 / sum_mt psum[row][mt]
// ============================================================================
__global__ __launch_bounds__(256) void rsum_kernel()
{
    int i = blockIdx.x * 256 + threadIdx.x;
    if (i < BRN * NN) {
        const float4* p = (const float4*)(g_psum + (size_t)i * 32);
        float s = 0.f;
        #pragma unroll
        for (int k = 0; k < 8; k++) {
            float4 v = p[k];
            s += v.x + v.y + v.z + v.w;
        }
        g_rinv[i] = 1.f / s;
    }
}

// ============================================================================
// Kernel 4: out[c,m] = (a'.rinv)@e + rinv_m*(b'@e^T) + bo; de-regionize.
// 64c x 128m tile, 256 thr, K-chunks of 64.
// ============================================================================
#define AS2 72
#define PS1 136
#define PS2 72
__global__ __launch_bounds__(256, 1) void out_kernel(
    const float* __restrict__ bo, float* __restrict__ outp)
{
    extern __shared__ char smo[];
    __nv_bfloat16* Ah  = (__nv_bfloat16*)smo;                 // [64][72]
    __nv_bfloat16* Al  = Ah + 64 * AS2;
    __nv_bfloat16* Bh  = Al + 64 * AS2;                       // [64][72]
    __nv_bfloat16* Bl  = Bh + 64 * AS2;
    __nv_bfloat16* P1h = Bl + 64 * AS2;                       // [64][136]
    __nv_bfloat16* P1l = P1h + 64 * PS1;
    __nv_bfloat16* P2h = P1l + 64 * PS1;                      // [128][72]
    __nv_bfloat16* P2l = P2h + 128 * PS2;
    __shared__ float rm[128];

    int mt = blockIdx.x, brr = blockIdx.y;
    int m0 = mt << 7;
    int t = threadIdx.x, lane = t & 31, w = t >> 5;
    int wc = (w >> 2) << 5, wm = (w & 3) << 5;

    const float* ag = g_a + (size_t)brr * CC * NN;
    const float* bg = g_b + (size_t)brr * CC * NN;
    const __nv_bfloat16* Phg = g_Ph + (size_t)brr * NN * NN;
    const __nv_bfloat16* Plg = g_Pl + (size_t)brr * NN * NN;

    if (t < 128) rm[t] = g_rinv[brr * NN + m0 + t];

    float acc1[2][4][4], acc2[2][4][4];
    #pragma unroll
    for (int i = 0; i < 2; i++)
        #pragma unroll
        for (int j = 0; j < 4; j++)
            #pragma unroll
            for (int k = 0; k < 4; k++) { acc1[i][j][k] = 0.f; acc2[i][j][k] = 0.f; }

    for (int kt = 0; kt < 64; kt++) {
        int n0 = kt << 6;
        __syncthreads();
        // A (a' * rinv) and B (b') tiles: [64c][64j] fp32 -> split
        #pragma unroll
        for (int it = 0; it < 4; it++) {
            int idx = t + (it << 8);
            int c = idx >> 4, f = idx & 15;
            float4 rv = *(const float4*)&g_rinv[brr * NN + n0 + (f << 2)];
            float4 va = *(const float4*)&ag[(size_t)c * NN + n0 + (f << 2)];
            va.x *= rv.x; va.y *= rv.y; va.z *= rv.z; va.w *= rv.w;
            split_store4(va, Ah + c * AS2 + (f << 2), Al + c * AS2 + (f << 2));
            float4 vb = *(const float4*)&bg[(size_t)c * NN + n0 + (f << 2)];
            split_store4(vb, Bh + c * AS2 + (f << 2), Bl + c * AS2 + (f << 2));
        }
        // P1: [64j][128m] direct bf16 copies
        #pragma unroll
        for (int it = 0; it < 8; it++) {
            int idx = t + (it << 8);
            int pl = idx >> 10, rem = idx & 1023;
            int j = rem >> 4, f = rem & 15;
            const __nv_bfloat16* s = (pl ? Plg : Phg);
            __nv_bfloat16* d = (pl ? P1l : P1h);
            *(uint4*)(d + j * PS1 + (f << 3)) =
                *(const uint4*)(s + (size_t)(n0 + j) * NN + m0 + (f << 3));
        }
        // P2: [128i][64j]
        #pragma unroll
        for (int it = 0; it < 8; it++) {
            int idx = t + (it << 8);
            int pl = idx >> 10, rem = idx & 1023;
            int i = rem >> 3, f = rem & 7;
            const __nv_bfloat16* s = (pl ? Plg : Phg);
            __nv_bfloat16* d = (pl ? P2l : P2h);
            *(uint4*)(d + i * PS2 + (f << 3)) =
                *(const uint4*)(s + (size_t)(m0 + i) * NN + n0 + (f << 3));
        }
        __syncthreads();

        int arow = wc + (lane & 15);
        int trow = lane & 15;
        int tcol = wm + ((lane >> 4) << 3);
        int nrow = wm + (lane & 7) + ((lane >> 4) << 3);
        #pragma unroll
        for (int kk = 0; kk < 4; kk++) {
            int acol = (kk << 4) + ((lane >> 4) << 3);
            int ncol = (kk << 4) + (lane & 8);
            // ---- term 1: a~ @ P1 ----
            {
                unsigned ah[2][4], al[2][4], p1h[4][2], p1l[4][2];
                #pragma unroll
                for (int mi = 0; mi < 2; mi++) {
                    ldsm4(ah[mi], sptr(Ah + (arow + mi * 16) * AS2 + acol));
                    ldsm4(al[mi], sptr(Al + (arow + mi * 16) * AS2 + acol));
                }
                #pragma unroll
                for (int nb = 0; nb < 2; nb++) {
                    unsigned r[4];
                    ldsm4t(r, sptr(P1h + ((kk << 4) + trow) * PS1 + tcol + nb * 16));
                    p1h[nb*2][0]=r[0]; p1h[nb*2][1]=r[1];
                    p1h[nb*2+1][0]=r[2]; p1h[nb*2+1][1]=r[3];
                    ldsm4t(r, sptr(P1l + ((kk << 4) + trow) * PS1 + tcol + nb * 16));
                    p1l[nb*2][0]=r[0]; p1l[nb*2][1]=r[1];
                    p1l[nb*2+1][0]=r[2]; p1l[nb*2+1][1]=r[3];
                }
                #pragma unroll
                for (int mi = 0; mi < 2; mi++)
                    #pragma unroll
                    for (int ni = 0; ni < 4; ni++) {
                        mma_bf16(acc1[mi][ni], ah[mi], p1h[ni][0], p1h[ni][1]);
                        mma_bf16(acc1[mi][ni], al[mi], p1h[ni][0], p1h[ni][1]);
                        mma_bf16(acc1[mi][ni], ah[mi], p1l[ni][0], p1l[ni][1]);
                    }
            }
            // ---- term 2: b' @ P2^T ----
            {
                unsigned bh2[2][4], bl2[2][4], p2h[4][2], p2l[4][2];
                #pragma unroll
                for (int mi = 0; mi < 2; mi++) {
                    ldsm4(bh2[mi], sptr(Bh + (arow + mi * 16) * AS2 + acol));
                    ldsm4(bl2[mi], sptr(Bl + (arow + mi * 16) * AS2 + acol));
                }
                #pragma unroll
                for (int nb = 0; nb < 2; nb++) {
                    unsigned r[4];
                    ldsm4(r, sptr(P2h + (nrow + nb * 16) * PS2 + ncol));
                    p2h[nb*2][0]=r[0]; p2h[nb*2][1]=r[1];
                    p2h[nb*2+1][0]=r[2]; p2h[nb*2+1][1]=r[3];
                    ldsm4(r, sptr(P2l + (nrow + nb * 16) * PS2 + ncol));
                    p2l[nb*2][0]=r[0]; p2l[nb*2][1]=r[1];
                    p2l[nb*2+1][0]=r[2]; p2l[nb*2+1][1]=r[3];
                }
                #pragma unroll
                for (int mi = 0; mi < 2; mi++)
                    #pragma unroll
                    for (int ni = 0; ni < 4; ni++) {
                        mma_bf16(acc2[mi][ni], bh2[mi], p2h[ni][0], p2h[ni][1]);
                        mma_bf16(acc2[mi][ni], bl2[mi], p2h[ni][0], p2h[ni][1]);
                        mma_bf16(acc2[mi][ni], bh2[mi], p2l[ni][0], p2l[ni][1]);
                    }
            }
        }
    }

    // ---- epilogue: + rinv_m * term2 + bo, de-regionized store ----
    int bb = brr >> 2, rr = brr & 3;
    int hbase = (rr >> 1) << 6, wbase = (rr & 1) << 6;
    int rloc = lane >> 2, cloc = (lane & 3) << 1;
    #pragma unroll
    for (int mi = 0; mi < 2; mi++) {
        int c0 = wc + mi * 16 + rloc, c1 = c0 + 8;
        float bo0 = bo[c0], bo1 = bo[c1];
        #pragma unroll
        for (int ni = 0; ni < 4; ni++) {
            int mcol = wm + ni * 8 + cloc;
            float rv0 = rm[mcol], rv1 = rm[mcol + 1];
            float f0 = acc1[mi][ni][0] + rv0 * acc2[mi][ni][0] + bo0;
            float f1 = acc1[mi][ni][1] + rv1 * acc2[mi][ni][1] + bo0;
            float f2 = acc1[mi][ni][2] + rv0 * acc2[mi][ni][2] + bo1;
            float f3 = acc1[mi][ni][3] + rv1 * acc2[mi][ni][3] + bo1;
            int n = m0 + mcol;
            int h = hbase + (n >> 6), ww = wbase + (n & 63);
            *(float2*)(outp + (((size_t)(bb * 64 + c0)) << 14) + (h << 7) + ww) =
                make_float2(f0, f1);
            *(float2*)(outp + (((size_t)(bb * 64 + c1)) << 14) + (h << 7) + ww) =
                make_float2(f2, f3);
        }
    }
}

// ============================================================================
extern "C" void kernel_launch(void* const* d_in, const int* in_sizes, int n_in,
                              void* d_out, int out_size)
{
    const float* x  = (const float*)d_in[0];
    const float* Wq = (const float*)d_in[1];
    const float* bq = (const float*)d_in[2];
    const float* Wk = (const float*)d_in[3];
    const float* bk = (const float*)d_in[4];
    const float* Wa = (const float*)d_in[5];
    const float* ba = (const float*)d_in[6];
    const float* Wb = (const float*)d_in[7];
    const float* bb = (const float*)d_in[8];
    const float* Wo = (const float*)d_in[9];
    const float* bo = (const float*)d_in[10];

    cudaFuncSetAttribute(score_kernel,
                         cudaFuncAttributeMaxDynamicSharedMemorySize, 73728);
    cudaFuncSetAttribute(out_kernel,
                         cudaFuncAttributeMaxDynamicSharedMemorySize, 110592);

    combine_w_kernel<<<1, 256>>>(Wo, Wa, ba, Wb, bb);
    conv_kernel<<<512, 256>>>(x, Wq, bq, Wk, bk);
    score_kernel<<<dim3(32, 32, 8), 256, 73728>>>();
    rsum_kernel<<<128, 256>>>();
    out_kernel<<<dim3(32, 8), 256, 110592>>>(bo, (float*)d_out);
}

// round 5
// speedup vs baseline: 4.7974x; 1.3860x over previous
#include <cuda_runtime.h>
#include <cuda_bf16.h>
#include <cuda_fp16.h>

#define CC   64
#define NN   4096
#define BRN  8
#define HW   128

// ---------------- scratch ----------------
__device__ __nv_bfloat16 g_qh[BRN * NN * CC];   // q/8, layout [br][n][c]
__device__ __nv_bfloat16 g_ql[BRN * NN * CC];
__device__ __nv_bfloat16 g_kh[BRN * NN * CC];   // k,   layout [br][m][c]
__device__ __nv_bfloat16 g_kl[BRN * NN * CC];
__device__ __half g_ah[BRN * CC * NN];          // a' = (Wo Wa)x + Wo ba, fp16
__device__ __half g_bh[BRN * CC * NN];          // b'
__device__ __half g_P[(size_t)BRN * NN * NN];   // e = exp(S), fp16
__device__ float g_psum[BRN * NN * 32];
__device__ float g_rinv[BRN * NN];
__device__ float g_W2a[CC * CC], g_W2b[CC * CC], g_b2a[CC], g_b2b[CC];

// ---------------- helpers ----------------
__device__ __forceinline__ unsigned sptr(const void* p) {
    return (unsigned)__cvta_generic_to_shared(p);
}
__device__ __forceinline__ void ldsm4(unsigned* r, unsigned a) {
    asm volatile("ldmatrix.sync.aligned.m8n8.x4.shared.b16 {%0,%1,%2,%3},[%4];"
                 : "=r"(r[0]), "=r"(r[1]), "=r"(r[2]), "=r"(r[3]) : "r"(a));
}
__device__ __forceinline__ void ldsm4t(unsigned* r, unsigned a) {
    asm volatile("ldmatrix.sync.aligned.m8n8.x4.trans.shared.b16 {%0,%1,%2,%3},[%4];"
                 : "=r"(r[0]), "=r"(r[1]), "=r"(r[2]), "=r"(r[3]) : "r"(a));
}
__device__ __forceinline__ void mma_bf16(float* d, const unsigned* a,
                                         unsigned b0, unsigned b1) {
    asm volatile("mma.sync.aligned.m16n8k16.row.col.f32.bf16.bf16.f32 "
                 "{%0,%1,%2,%3},{%4,%5,%6,%7},{%8,%9},{%0,%1,%2,%3};"
                 : "+f"(d[0]), "+f"(d[1]), "+f"(d[2]), "+f"(d[3])
                 : "r"(a[0]), "r"(a[1]), "r"(a[2]), "r"(a[3]), "r"(b0), "r"(b1));
}
__device__ __forceinline__ void mma_f16(float* d, const unsigned* a,
                                        unsigned b0, unsigned b1) {
    asm volatile("mma.sync.aligned.m16n8k16.row.col.f32.f16.f16.f32 "
                 "{%0,%1,%2,%3},{%4,%5,%6,%7},{%8,%9},{%0,%1,%2,%3};"
                 : "+f"(d[0]), "+f"(d[1]), "+f"(d[2]), "+f"(d[3])
                 : "r"(a[0]), "r"(a[1]), "r"(a[2]), "r"(a[3]), "r"(b0), "r"(b1));
}
__device__ __forceinline__ float fast_exp(float s) {
    float t = s * 1.4426950408889634f;
    t = fmaxf(t, -125.0f);
    float fl = rintf(t);
    float fr = t - fl;
    float p = 1.5403631e-4f;
    p = fmaf(p, fr, 1.3333558146428443e-3f);
    p = fmaf(p, fr, 9.618129107628477e-3f);
    p = fmaf(p, fr, 5.550410866482158e-2f);
    p = fmaf(p, fr, 2.402265069591007e-1f);
    p = fmaf(p, fr, 6.931471805599453e-1f);
    p = fmaf(p, fr, 1.0f);
    return __int_as_float(((int)fl + 127) << 23) * p;
}
__device__ __forceinline__ void split_store4(float4 v, __nv_bfloat16* dh,
                                             __nv_bfloat16* dl) {
    __nv_bfloat162 h01 = __float22bfloat162_rn(make_float2(v.x, v.y));
    __nv_bfloat162 h23 = __float22bfloat162_rn(make_float2(v.z, v.w));
    __nv_bfloat162 l01 = __float22bfloat162_rn(make_float2(
        v.x - __bfloat162float(h01.x), v.y - __bfloat162float(h01.y)));
    __nv_bfloat162 l23 = __float22bfloat162_rn(make_float2(
        v.z - __bfloat162float(h23.x), v.w - __bfloat162float(h23.y)));
    *(__nv_bfloat162*)(dh)     = h01;
    *(__nv_bfloat162*)(dh + 2) = h23;
    *(__nv_bfloat162*)(dl)     = l01;
    *(__nv_bfloat162*)(dl + 2) = l23;
}

// ============================================================================
// Kernel 0: combined weights  W2a = Wo@Wa, b2a = Wo@ba (likewise b)
// ============================================================================
__global__ __launch_bounds__(256) void combine_w_kernel(
    const float* __restrict__ Wo,
    const float* __restrict__ Wa, const float* __restrict__ ba,
    const float* __restrict__ Wb, const float* __restrict__ bb)
{
    __shared__ float so[4096], sa[4096], sb[4096];
    int t = threadIdx.x;
    for (int i = t; i < 4096; i += 256) { so[i] = Wo[i]; sa[i] = Wa[i]; sb[i] = Wb[i]; }
    __syncthreads();
    for (int e = t; e < 4096; e += 256) {
        int o = e >> 6, c = e & 63;
        float s1 = 0.f, s2 = 0.f;
        for (int k = 0; k < 64; k++) {
            s1 += so[o * 64 + k] * sa[k * 64 + c];
            s2 += so[o * 64 + k] * sb[k * 64 + c];
        }
        g_W2a[e] = s1; g_W2b[e] = s2;
    }
    if (t < 64) {
        float s1 = 0.f, s2 = 0.f;
        for (int k = 0; k < 64; k++) {
            s1 += so[t * 64 + k] * ba[k];
            s2 += so[t * 64 + k] * bb[k];
        }
        g_b2a[t] = s1; g_b2b[t] = s2;
    }
}

// ============================================================================
// Kernel 1: 1x1 convs -> q/8,k bf16 planes [br][n][c]; a',b' fp16 [br][c][n]
// ============================================================================
__global__ __launch_bounds__(256) void conv_kernel(
    const float* __restrict__ x,
    const float* __restrict__ Wq, const float* __restrict__ bq,
    const float* __restrict__ Wk, const float* __restrict__ bk)
{
    __shared__ float xs[64 * 64];
    int blk = blockIdx.x;
    int br = blk >> 6, chunk = blk & 63;
    int b = br >> 2, r = br & 3;
    int n0 = chunk << 6;
    int h = ((r >> 1) << 6) + chunk;
    int wb = (r & 1) << 6;

    const float* xrow = x + (size_t)(b * CC) * (HW * HW) + (size_t)h * HW + wb;
    for (int idx = threadIdx.x; idx < 64 * 64; idx += 256) {
        int c = idx >> 6, px = idx & 63;
        xs[idx] = xrow[(size_t)c * (HW * HW) + px];
    }
    __syncthreads();

    int px = threadIdx.x & 63;
    int conv = threadIdx.x >> 6;
    const float *W, *bi;
    if      (conv == 0) { W = Wq;    bi = bq;    }
    else if (conv == 1) { W = Wk;    bi = bk;    }
    else if (conv == 2) { W = g_W2a; bi = g_b2a; }
    else                { W = g_W2b; bi = g_b2b; }

    float acc[64];
    #pragma unroll
    for (int o = 0; o < 64; o++) acc[o] = bi[o];
    for (int c = 0; c < 64; c++) {
        float xv = xs[(c << 6) + px];
        #pragma unroll
        for (int o = 0; o < 64; o++) acc[o] += W[o * 64 + c] * xv;
    }

    if (conv < 2) {
        float sc = (conv == 0) ? 0.125f : 1.0f;
        __nv_bfloat16* ph = (conv == 0 ? g_qh : g_kh);
        __nv_bfloat16* pl = (conv == 0 ? g_ql : g_kl);
        size_t row = ((size_t)br * NN + n0 + px) * 64;
        #pragma unroll
        for (int o = 0; o < 64; o += 4) {
            float4 v = make_float4(acc[o] * sc, acc[o+1] * sc,
                                   acc[o+2] * sc, acc[o+3] * sc);
            split_store4(v, ph + row + o, pl + row + o);
        }
    } else {
        __half* outp = (conv == 2 ? g_ah : g_bh);
        size_t base = (size_t)br * CC * NN + n0 + px;
        #pragma unroll
        for (int o = 0; o < 64; o++) outp[base + (size_t)o * NN] = __float2half(acc[o]);
    }
}

// ============================================================================
// Kernel 2: e = exp(q.k) via 3-pass bf16 HMMA; 128x128 tile; fp16 e + psums.
// ============================================================================
#define QS 72
__global__ __launch_bounds__(256, 1) void score_kernel()
{
    extern __shared__ __nv_bfloat16 smq[];
    __nv_bfloat16* QH = smq;
    __nv_bfloat16* QL = QH + 128 * QS;
    __nv_bfloat16* KH = QL + 128 * QS;
    __nv_bfloat16* KL = KH + 128 * QS;
    __shared__ float pr2[8][64];

    int mt = blockIdx.x, nt = blockIdx.y, brr = blockIdx.z;
    int n0 = nt << 7, m0 = mt << 7;
    int t = threadIdx.x, lane = t & 31, w = t >> 5;
    int wn = (w >> 2) << 6, wm = (w & 3) << 5;

    for (int i = t; i < 512; i += 256) ((float*)pr2)[i] = 0.f;

    {
        const __nv_bfloat16* srcs[4] = {g_qh, g_ql, g_kh, g_kl};
        __nv_bfloat16* dsts[4] = {QH, QL, KH, KL};
        #pragma unroll
        for (int pl = 0; pl < 4; pl++) {
            int rb = (pl < 2) ? n0 : m0;
            const __nv_bfloat16* s = srcs[pl];
            __nv_bfloat16* d = dsts[pl];
            #pragma unroll
            for (int it = 0; it < 4; it++) {
                int idx = t + (it << 8);
                int row = idx >> 3, f = idx & 7;
                *(uint4*)(d + row * QS + (f << 3)) =
                    *((const uint4*)(s + ((size_t)brr * NN + rb + row) * 64) + f);
            }
        }
    }
    __syncthreads();

    float acc[4][4][4];
    #pragma unroll
    for (int i = 0; i < 4; i++)
        #pragma unroll
        for (int j = 0; j < 4; j++)
            #pragma unroll
            for (int k = 0; k < 4; k++) acc[i][j][k] = 0.f;

    int arow = wn + (lane & 15);
    int brow = wm + (lane & 7) + ((lane >> 4) << 3);
    #pragma unroll
    for (int kk = 0; kk < 4; kk++) {
        int acol = (kk << 4) + ((lane >> 4) << 3);
        int bcol = (kk << 4) + (lane & 8);
        unsigned qh[4][4], ql[4][4], kh[4][2], kl[4][2];
        #pragma unroll
        for (int mi = 0; mi < 4; mi++) {
            ldsm4(qh[mi], sptr(QH + (arow + mi * 16) * QS + acol));
            ldsm4(ql[mi], sptr(QL + (arow + mi * 16) * QS + acol));
        }
        #pragma unroll
        for (int nb = 0; nb < 2; nb++) {
            unsigned r[4];
            ldsm4(r, sptr(KH + (brow + nb * 16) * QS + bcol));
            kh[nb*2][0]=r[0]; kh[nb*2][1]=r[1]; kh[nb*2+1][0]=r[2]; kh[nb*2+1][1]=r[3];
            ldsm4(r, sptr(KL + (brow + nb * 16) * QS + bcol));
            kl[nb*2][0]=r[0]; kl[nb*2][1]=r[1]; kl[nb*2+1][0]=r[2]; kl[nb*2+1][1]=r[3];
        }
        #pragma unroll
        for (int mi = 0; mi < 4; mi++)
            #pragma unroll
            for (int ni = 0; ni < 4; ni++) {
                mma_bf16(acc[mi][ni], qh[mi], kh[ni][0], kh[ni][1]);
                mma_bf16(acc[mi][ni], ql[mi], kh[ni][0], kh[ni][1]);
                mma_bf16(acc[mi][ni], qh[mi], kl[ni][0], kl[ni][1]);
            }
    }

    // exp + fp16 store + deterministic per-warp row partials
    size_t Pbase = (size_t)brr * NN * NN;
    int rloc = lane >> 2;
    int cloc = (lane & 3) << 1;
    #pragma unroll
    for (int mi = 0; mi < 4; mi++) {
        float s0 = 0.f, s1 = 0.f;
        #pragma unroll
        for (int ni = 0; ni < 4; ni++) {
            float e0 = fast_exp(acc[mi][ni][0]);
            float e1 = fast_exp(acc[mi][ni][1]);
            float e2 = fast_exp(acc[mi][ni][2]);
            float e3 = fast_exp(acc[mi][ni][3]);
            s0 += e0 + e1; s1 += e2 + e3;
            int row0 = n0 + wn + mi * 16 + rloc;
            int col  = m0 + wm + ni * 8 + cloc;
            *(__half2*)(g_P + Pbase + (size_t)row0 * NN + col) =
                __float22half2_rn(make_float2(e0, e1));
            *(__half2*)(g_P + Pbase + (size_t)(row0 + 8) * NN + col) =
                __float22half2_rn(make_float2(e2, e3));
        }
        s0 += __shfl_xor_sync(0xffffffffu, s0, 1);
        s0 += __shfl_xor_sync(0xffffffffu, s0, 2);
        s1 += __shfl_xor_sync(0xffffffffu, s1, 1);
        s1 += __shfl_xor_sync(0xffffffffu, s1, 2);
        if ((lane & 3) == 0) {
            pr2[w][mi * 16 + rloc]     = pr2[w][mi * 16 + rloc] + s0;
            pr2[w][mi * 16 + rloc + 8] = pr2[w][mi * 16 + rloc + 8] + s1;
        }
    }
    __syncthreads();
    if (t < 128) {
        int g4 = (t >> 6) << 2, lr = t & 63;
        float s = pr2[g4][lr] + pr2[g4+1][lr] + pr2[g4+2][lr] + pr2[g4+3][lr];
        g_psum[((size_t)brr * NN + n0 + t) * 32 + mt] = s;
    }
}

// ============================================================================
// Kernel 3: rinv[row] = 1 / sum_mt psum[row][mt]
// ============================================================================
__global__ __launch_bounds__(256) void rsum_kernel()
{
    int i = blockIdx.x * 256 + threadIdx.x;
    if (i < BRN * NN) {
        const float4* p = (const float4*)(g_psum + (size_t)i * 32);
        float s = 0.f;
        #pragma unroll
        for (int k = 0; k < 8; k++) {
            float4 v = p[k];
            s += v.x + v.y + v.z + v.w;
        }
        g_rinv[i] = 1.f / s;
    }
}

// ============================================================================
// Kernel 4: out[c,m] = (a'.rinv)@e + rinv_m*(b'@e^T) + bo; single-pass fp16.
// 64c x 128m tile, 256 thr, K-chunks of 64.
// ============================================================================
#define AS2 72
#define PS1 136
#define PS2 72
__global__ __launch_bounds__(256, 1) void out_kernel(
    const float* __restrict__ bo, float* __restrict__ outp)
{
    extern __shared__ char smo[];
    __half* Ah = (__half*)smo;              // [64][72]
    __half* Bh = Ah + 64 * AS2;             // [64][72]
    __half* P1 = Bh + 64 * AS2;             // [64][136]
    __half* P2 = P1 + 64 * PS1;             // [128][72]
    __shared__ float rm[128];

    int mt = blockIdx.x, brr = blockIdx.y;
    int m0 = mt << 7;
    int t = threadIdx.x, lane = t & 31, w = t >> 5;
    int wc = (w >> 2) << 5, wm = (w & 3) << 5;

    const __half* ag = g_ah + (size_t)brr * CC * NN;
    const __half* bg = g_bh + (size_t)brr * CC * NN;
    const __half* Pg = g_P + (size_t)brr * NN * NN;

    if (t < 128) rm[t] = g_rinv[brr * NN + m0 + t];

    float acc1[2][4][4], acc2[2][4][4];
    #pragma unroll
    for (int i = 0; i < 2; i++)
        #pragma unroll
        for (int j = 0; j < 4; j++)
            #pragma unroll
            for (int k = 0; k < 4; k++) { acc1[i][j][k] = 0.f; acc2[i][j][k] = 0.f; }

    for (int kt = 0; kt < 64; kt++) {
        int n0 = kt << 6;
        __syncthreads();
        // A = a' * rinv (fp32 multiply, round to fp16), B = b' straight copy
        #pragma unroll
        for (int it = 0; it < 2; it++) {
            int idx = t + (it << 8);          // 0..511
            int c = idx >> 3, f = idx & 7;
            int j0 = f << 3;
            uint4 va = *(const uint4*)(ag + (size_t)c * NN + n0 + j0);
            float4 r0 = *(const float4*)&g_rinv[brr * NN + n0 + j0];
            float4 r1 = *(const float4*)&g_rinv[brr * NN + n0 + j0 + 4];
            __half2* vh = (__half2*)&va;
            float2 f0 = __half22float2(vh[0]); f0.x *= r0.x; f0.y *= r0.y;
            vh[0] = __float22half2_rn(f0);
            float2 f1 = __half22float2(vh[1]); f1.x *= r0.z; f1.y *= r0.w;
            vh[1] = __float22half2_rn(f1);
            float2 f2 = __half22float2(vh[2]); f2.x *= r1.x; f2.y *= r1.y;
            vh[2] = __float22half2_rn(f2);
            float2 f3 = __half22float2(vh[3]); f3.x *= r1.z; f3.y *= r1.w;
            vh[3] = __float22half2_rn(f3);
            *(uint4*)(Ah + c * AS2 + j0) = va;
            uint4 vb = *(const uint4*)(bg + (size_t)c * NN + n0 + j0);
            *(uint4*)(Bh + c * AS2 + j0) = vb;
        }
        // P1: [64j][128m]
        #pragma unroll
        for (int it = 0; it < 4; it++) {
            int idx = t + (it << 8);          // 0..1023
            int j = idx >> 4, f = idx & 15;
            *(uint4*)(P1 + j * PS1 + (f << 3)) =
                *(const uint4*)(Pg + (size_t)(n0 + j) * NN + m0 + (f << 3));
        }
        // P2: [128i][64j]
        #pragma unroll
        for (int it = 0; it < 4; it++) {
            int idx = t + (it << 8);          // 0..1023
            int i = idx >> 3, f = idx & 7;
            *(uint4*)(P2 + i * PS2 + (f << 3)) =
                *(const uint4*)(Pg + (size_t)(m0 + i) * NN + n0 + (f << 3));
        }
        __syncthreads();

        int arow = wc + (lane & 15);
        int trow = lane & 15;
        int tcol = wm + ((lane >> 4) << 3);
        int nrow = wm + (lane & 7) + ((lane >> 4) << 3);
        #pragma unroll
        for (int kk = 0; kk < 4; kk++) {
            int acol = (kk << 4) + ((lane >> 4) << 3);
            int ncol = (kk << 4) + (lane & 8);
            // ---- term 1: a~ @ P1 ----
            {
                unsigned ah[2][4], p1[4][2];
                #pragma unroll
                for (int mi = 0; mi < 2; mi++)
                    ldsm4(ah[mi], sptr(Ah + (arow + mi * 16) * AS2 + acol));
                #pragma unroll
                for (int nb = 0; nb < 2; nb++) {
                    unsigned r[4];
                    ldsm4t(r, sptr(P1 + ((kk << 4) + trow) * PS1 + tcol + nb * 16));
                    p1[nb*2][0]=r[0]; p1[nb*2][1]=r[1];
                    p1[nb*2+1][0]=r[2]; p1[nb*2+1][1]=r[3];
                }
                #pragma unroll
                for (int mi = 0; mi < 2; mi++)
                    #pragma unroll
                    for (int ni = 0; ni < 4; ni++)
                        mma_f16(acc1[mi][ni], ah[mi], p1[ni][0], p1[ni][1]);
            }
            // ---- term 2: b' @ P2^T ----
            {
                unsigned bh2[2][4], p2[4][2];
                #pragma unroll
                for (int mi = 0; mi < 2; mi++)
                    ldsm4(bh2[mi], sptr(Bh + (arow + mi * 16) * AS2 + acol));
                #pragma unroll
                for (int nb = 0; nb < 2; nb++) {
                    unsigned r[4];
                    ldsm4(r, sptr(P2 + (nrow + nb * 16) * PS2 + ncol));
                    p2[nb*2][0]=r[0]; p2[nb*2][1]=r[1];
                    p2[nb*2+1][0]=r[2]; p2[nb*2+1][1]=r[3];
                }
                #pragma unroll
                for (int mi = 0; mi < 2; mi++)
                    #pragma unroll
                    for (int ni = 0; ni < 4; ni++)
                        mma_f16(acc2[mi][ni], bh2[mi], p2[ni][0], p2[ni][1]);
            }
        }
    }

    // ---- epilogue: term1 + rinv_m * term2 + bo, de-regionized store ----
    int bb = brr >> 2, rr = brr & 3;
    int hbase = (rr >> 1) << 6, wbase = (rr & 1) << 6;
    int rloc = lane >> 2, cloc = (lane & 3) << 1;
    #pragma unroll
    for (int mi = 0; mi < 2; mi++) {
        int c0 = wc + mi * 16 + rloc, c1 = c0 + 8;
        float bo0 = bo[c0], bo1 = bo[c1];
        #pragma unroll
        for (int ni = 0; ni < 4; ni++) {
            int mcol = wm + ni * 8 + cloc;
            float rv0 = rm[mcol], rv1 = rm[mcol + 1];
            float f0 = acc1[mi][ni][0] + rv0 * acc2[mi][ni][0] + bo0;
            float f1 = acc1[mi][ni][1] + rv1 * acc2[mi][ni][1] + bo0;
            float f2 = acc1[mi][ni][2] + rv0 * acc2[mi][ni][2] + bo1;
            float f3 = acc1[mi][ni][3] + rv1 * acc2[mi][ni][3] + bo1;
            int n = m0 + mcol;
            int h = hbase + (n >> 6), ww = wbase + (n & 63);
            *(float2*)(outp + (((size_t)(bb * 64 + c0)) << 14) + (h << 7) + ww) =
                make_float2(f0, f1);
            *(float2*)(outp + (((size_t)(bb * 64 + c1)) << 14) + (h << 7) + ww) =
                make_float2(f2, f3);
        }
    }
}

// ============================================================================
extern "C" void kernel_launch(void* const* d_in, const int* in_sizes, int n_in,
                              void* d_out, int out_size)
{
    const float* x  = (const float*)d_in[0];
    const float* Wq = (const float*)d_in[1];
    const float* bq = (const float*)d_in[2];
    const float* Wk = (const float*)d_in[3];
    const float* bk = (const float*)d_in[4];
    const float* Wa = (const float*)d_in[5];
    const float* ba = (const float*)d_in[6];
    const float* Wb = (const float*)d_in[7];
    const float* bb = (const float*)d_in[8];
    const float* Wo = (const float*)d_in[9];
    const float* bo = (const float*)d_in[10];

    cudaFuncSetAttribute(score_kernel,
                         cudaFuncAttributeMaxDynamicSharedMemorySize, 73728);
    cudaFuncSetAttribute(out_kernel,
                         cudaFuncAttributeMaxDynamicSharedMemorySize, 54272);

    combine_w_kernel<<<1, 256>>>(Wo, Wa, ba, Wb, bb);
    conv_kernel<<<512, 256>>>(x, Wq, bq, Wk, bk);
    score_kernel<<<dim3(32, 32, 8), 256, 73728>>>();
    rsum_kernel<<<128, 256>>>();
    out_kernel<<<dim3(32, 8), 256, 54272>>>(bo, (float*)d_out);
}

// round 7
// speedup vs baseline: 6.3055x; 1.3143x over previous
#include <cuda_runtime.h>
#include <cuda_fp16.h>

#define CC   64
#define NN   4096
#define BRN  8
#define HW   128

// ---------------- scratch ----------------
__device__ __half g_q16[BRN * NN * CC];         // q/8, layout [br][n][c]
__device__ __half g_k16[BRN * NN * CC];         // k,   layout [br][m][c]
__device__ __half g_ah[BRN * CC * NN];          // a' = (Wo Wa)x + Wo ba
__device__ __half g_bh[BRN * CC * NN];          // b'
__device__ __half g_P[(size_t)BRN * NN * NN];   // e = exp(S), fp16
__device__ float g_psum[BRN * NN * 32];
__device__ float g_rinv[BRN * NN];
__device__ float g_W2a[CC * CC], g_W2b[CC * CC], g_b2a[CC], g_b2b[CC];

// ---------------- helpers ----------------
__device__ __forceinline__ unsigned sptr(const void* p) {
    return (unsigned)__cvta_generic_to_shared(p);
}
__device__ __forceinline__ void ldsm4(unsigned* r, unsigned a) {
    asm volatile("ldmatrix.sync.aligned.m8n8.x4.shared.b16 {%0,%1,%2,%3},[%4];"
                 : "=r"(r[0]), "=r"(r[1]), "=r"(r[2]), "=r"(r[3]) : "r"(a));
}
__device__ __forceinline__ void ldsm4t(unsigned* r, unsigned a) {
    asm volatile("ldmatrix.sync.aligned.m8n8.x4.trans.shared.b16 {%0,%1,%2,%3},[%4];"
                 : "=r"(r[0]), "=r"(r[1]), "=r"(r[2]), "=r"(r[3]) : "r"(a));
}
__device__ __forceinline__ void mma_f16(float* d, const unsigned* a,
                                        unsigned b0, unsigned b1) {
    asm volatile("mma.sync.aligned.m16n8k16.row.col.f32.f16.f16.f32 "
                 "{%0,%1,%2,%3},{%4,%5,%6,%7},{%8,%9},{%0,%1,%2,%3};"
                 : "+f"(d[0]), "+f"(d[1]), "+f"(d[2]), "+f"(d[3])
                 : "r"(a[0]), "r"(a[1]), "r"(a[2]), "r"(a[3]), "r"(b0), "r"(b1));
}
__device__ __forceinline__ float fast_exp(float s) {
    s = fminf(fmaxf(s, -87.0f), 87.0f);
    float t = s * 1.4426950408889634f;
    float fl = rintf(t);
    float fr = t - fl;
    float p = 1.5403631e-4f;
    p = fmaf(p, fr, 1.3333558146428443e-3f);
    p = fmaf(p, fr, 9.618129107628477e-3f);
    p = fmaf(p, fr, 5.550410866482158e-2f);
    p = fmaf(p, fr, 2.402265069591007e-1f);
    p = fmaf(p, fr, 6.931471805599453e-1f);
    p = fmaf(p, fr, 1.0f);
    return __int_as_float(((int)fl + 127) << 23) * p;
}

// ============================================================================
// Kernel 0: combined weights  W2a = Wo@Wa, b2a = Wo@ba (likewise b)
// ============================================================================
__global__ __launch_bounds__(256) void combine_w_kernel(
    const float* __restrict__ Wo,
    const float* __restrict__ Wa, const float* __restrict__ ba,
    const float* __restrict__ Wb, const float* __restrict__ bb)
{
    __shared__ float so[4096], sa[4096], sb[4096];
    int t = threadIdx.x;
    for (int i = t; i < 4096; i += 256) { so[i] = Wo[i]; sa[i] = Wa[i]; sb[i] = Wb[i]; }
    __syncthreads();
    for (int e = t; e < 4096; e += 256) {
        int o = e >> 6, c = e & 63;
        float s1 = 0.f, s2 = 0.f;
        for (int k = 0; k < 64; k++) {
            s1 += so[o * 64 + k] * sa[k * 64 + c];
            s2 += so[o * 64 + k] * sb[k * 64 + c];
        }
        g_W2a[e] = s1; g_W2b[e] = s2;
    }
    if (t < 64) {
        float s1 = 0.f, s2 = 0.f;
        for (int k = 0; k < 64; k++) {
            s1 += so[t * 64 + k] * ba[k];
            s2 += so[t * 64 + k] * bb[k];
        }
        g_b2a[t] = s1; g_b2b[t] = s2;
    }
}

// ============================================================================
// Kernel 1: 1x1 convs -> q/8,k fp16 [br][n][c]; a',b' fp16 [br][c][n]
// ============================================================================
__global__ __launch_bounds__(256) void conv_kernel(
    const float* __restrict__ x,
    const float* __restrict__ Wq, const float* __restrict__ bq,
    const float* __restrict__ Wk, const float* __restrict__ bk)
{
    __shared__ float xs[64 * 64];
    int blk = blockIdx.x;
    int br = blk >> 6, chunk = blk & 63;
    int b = br >> 2, r = br & 3;
    int n0 = chunk << 6;
    int h = ((r >> 1) << 6) + chunk;
    int wb = (r & 1) << 6;

    const float* xrow = x + (size_t)(b * CC) * (HW * HW) + (size_t)h * HW + wb;
    for (int idx = threadIdx.x; idx < 64 * 64; idx += 256) {
        int c = idx >> 6, px = idx & 63;
        xs[idx] = xrow[(size_t)c * (HW * HW) + px];
    }
    __syncthreads();

    int px = threadIdx.x & 63;
    int conv = threadIdx.x >> 6;
    const float *W, *bi;
    if      (conv == 0) { W = Wq;    bi = bq;    }
    else if (conv == 1) { W = Wk;    bi = bk;    }
    else if (conv == 2) { W = g_W2a; bi = g_b2a; }
    else                { W = g_W2b; bi = g_b2b; }

    float acc[64];
    #pragma unroll
    for (int o = 0; o < 64; o++) acc[o] = bi[o];
    for (int c = 0; c < 64; c++) {
        float xv = xs[(c << 6) + px];
        #pragma unroll
        for (int o = 0; o < 64; o++) acc[o] += W[o * 64 + c] * xv;
    }

    if (conv < 2) {
        float sc = (conv == 0) ? 0.125f : 1.0f;
        __half* outp = (conv == 0 ? g_q16 : g_k16);
        size_t row = ((size_t)br * NN + n0 + px) * 64;
        #pragma unroll
        for (int o = 0; o < 64; o += 2)
            *(__half2*)(outp + row + o) =
                __float22half2_rn(make_float2(acc[o] * sc, acc[o + 1] * sc));
    } else {
        __half* outp = (conv == 2 ? g_ah : g_bh);
        size_t base = (size_t)br * CC * NN + n0 + px;
        #pragma unroll
        for (int o = 0; o < 64; o++) outp[base + (size_t)o * NN] = __float2half(acc[o]);
    }
}

// ============================================================================
// Kernel 2: e = exp(q.k) single-pass fp16 HMMA; 128x128 tile; smem-staged
//           coalesced fp16 store + deterministic partial row sums.
// ============================================================================
#define QS 72
#define PSS 136
__global__ __launch_bounds__(256, 2) void score_kernel()
{
    extern __shared__ __half smq[];
    __half* QH = smq;               // [128][72]
    __half* KH = smq + 128 * QS;    // [128][72]
    __half* Ps = smq;               // reuse: [128][136] staged e-tile
    __shared__ float pr2[8][64];

    int mt = blockIdx.x, nt = blockIdx.y, brr = blockIdx.z;
    int n0 = nt << 7, m0 = mt << 7;
    int t = threadIdx.x, lane = t & 31, w = t >> 5;
    int wn = (w >> 2) << 6, wm = (w & 3) << 5;

    for (int i = t; i < 512; i += 256) ((float*)pr2)[i] = 0.f;

    #pragma unroll
    for (int it = 0; it < 4; it++) {
        int idx = t + (it << 8);
        int row = idx >> 3, f = idx & 7;
        *(uint4*)(QH + row * QS + (f << 3)) =
            *((const uint4*)(g_q16 + ((size_t)brr * NN + n0 + row) * 64) + f);
        *(uint4*)(KH + row * QS + (f << 3)) =
            *((const uint4*)(g_k16 + ((size_t)brr * NN + m0 + row) * 64) + f);
    }
    __syncthreads();

    float acc[4][4][4];
    #pragma unroll
    for (int i = 0; i < 4; i++)
        #pragma unroll
        for (int j = 0; j < 4; j++)
            #pragma unroll
            for (int k = 0; k < 4; k++) acc[i][j][k] = 0.f;

    int arow = wn + (lane & 15);
    int brow = wm + (lane & 7) + ((lane >> 4) << 3);
    #pragma unroll
    for (int kk = 0; kk < 4; kk++) {
        int acol = (kk << 4) + ((lane >> 4) << 3);
        int bcol = (kk << 4) + (lane & 8);
        unsigned qh[4][4], kh[4][2];
        #pragma unroll
        for (int mi = 0; mi < 4; mi++)
            ldsm4(qh[mi], sptr(QH + (arow + mi * 16) * QS + acol));
        #pragma unroll
        for (int nb = 0; nb < 2; nb++) {
            unsigned r[4];
            ldsm4(r, sptr(KH + (brow + nb * 16) * QS + bcol));
            kh[nb*2][0]=r[0]; kh[nb*2][1]=r[1]; kh[nb*2+1][0]=r[2]; kh[nb*2+1][1]=r[3];
        }
        #pragma unroll
        for (int mi = 0; mi < 4; mi++)
            #pragma unroll
            for (int ni = 0; ni < 4; ni++)
                mma_f16(acc[mi][ni], qh[mi], kh[ni][0], kh[ni][1]);
    }
    __syncthreads();   // QH/KH ldsm reads done; Ps may overwrite

    // exp -> staged smem tile + per-warp row partial sums
    int rloc = lane >> 2;
    int cloc = (lane & 3) << 1;
    #pragma unroll
    for (int mi = 0; mi < 4; mi++) {
        float s0 = 0.f, s1 = 0.f;
        #pragma unroll
        for (int ni = 0; ni < 4; ni++) {
            float e0 = fast_exp(acc[mi][ni][0]);
            float e1 = fast_exp(acc[mi][ni][1]);
            float e2 = fast_exp(acc[mi][ni][2]);
            float e3 = fast_exp(acc[mi][ni][3]);
            s0 += e0 + e1; s1 += e2 + e3;
            int row0 = wn + mi * 16 + rloc;
            int col  = wm + ni * 8 + cloc;
            *(__half2*)(Ps + row0 * PSS + col) =
                __float22half2_rn(make_float2(e0, e1));
            *(__half2*)(Ps + (row0 + 8) * PSS + col) =
                __float22half2_rn(make_float2(e2, e3));
        }
        s0 += __shfl_xor_sync(0xffffffffu, s0, 1);
        s0 += __shfl_xor_sync(0xffffffffu, s0, 2);
        s1 += __shfl_xor_sync(0xffffffffu, s1, 1);
        s1 += __shfl_xor_sync(0xffffffffu, s1, 2);
        if ((lane & 3) == 0) {
            pr2[w][mi * 16 + rloc]     = pr2[w][mi * 16 + rloc] + s0;
            pr2[w][mi * 16 + rloc + 8] = pr2[w][mi * 16 + rloc + 8] + s1;
        }
    }
    __syncthreads();

    // coalesced global store of the e-tile
    size_t Pbase = (size_t)brr * NN * NN;
    #pragma unroll
    for (int it = 0; it < 8; it++) {
        int idx = t + (it << 8);
        int row = idx >> 4, f = idx & 15;
        *(uint4*)(g_P + Pbase + (size_t)(n0 + row) * NN + m0 + (f << 3)) =
            *(uint4*)(Ps + row * PSS + (f << 3));
    }
    if (t < 128) {
        int g4 = (t >> 6) << 2, lr = t & 63;
        float s = pr2[g4][lr] + pr2[g4+1][lr] + pr2[g4+2][lr] + pr2[g4+3][lr];
        g_psum[((size_t)brr * NN + n0 + t) * 32 + mt] = s;
    }
}

// ============================================================================
// Kernel 3: rinv[row] = 1 / sum_mt psum[row][mt]
// ============================================================================
__global__ __launch_bounds__(256) void rsum_kernel()
{
    int i = blockIdx.x * 256 + threadIdx.x;
    if (i < BRN * NN) {
        const float4* p = (const float4*)(g_psum + (size_t)i * 32);
        float s = 0.f;
        #pragma unroll
        for (int k = 0; k < 8; k++) {
            float4 v = p[k];
            s += v.x + v.y + v.z + v.w;
        }
        g_rinv[i] = 1.f / s;
    }
}

// ============================================================================
// Kernel 4: out[c,m] = (a'.rinv)@e + rinv_m*(b'@e^T) + bo; single-pass fp16.
// 64c x 128m tile, 256 thr, K-chunks of 64.
// ============================================================================
#define AS2 72
#define PS1 136
#define PS2 72
__global__ __launch_bounds__(256, 1) void out_kernel(
    const float* __restrict__ bo, float* __restrict__ outp)
{
    extern __shared__ char smo[];
    __half* Ah = (__half*)smo;              // [64][72]
    __half* Bh = Ah + 64 * AS2;             // [64][72]
    __half* P1 = Bh + 64 * AS2;             // [64][136]
    __half* P2 = P1 + 64 * PS1;             // [128][72]
    __shared__ float rm[128];

    int mt = blockIdx.x, brr = blockIdx.y;
    int m0 = mt << 7;
    int t = threadIdx.x, lane = t & 31, w = t >> 5;
    int wc = (w >> 2) << 5, wm = (w & 3) << 5;

    const __half* ag = g_ah + (size_t)brr * CC * NN;
    const __half* bg = g_bh + (size_t)brr * CC * NN;
    const __half* Pg = g_P + (size_t)brr * NN * NN;

    if (t < 128) rm[t] = g_rinv[brr * NN + m0 + t];

    float acc1[2][4][4], acc2[2][4][4];
    #pragma unroll
    for (int i = 0; i < 2; i++)
        #pragma unroll
        for (int j = 0; j < 4; j++)
            #pragma unroll
            for (int k = 0; k < 4; k++) { acc1[i][j][k] = 0.f; acc2[i][j][k] = 0.f; }

    for (int kt = 0; kt < 64; kt++) {
        int n0 = kt << 6;
        __syncthreads();
        // A = a' * rinv (fp32 multiply, round to fp16), B = b' straight copy
        #pragma unroll
        for (int it = 0; it < 2; it++) {
            int idx = t + (it << 8);          // 0..511
            int c = idx >> 3, f = idx & 7;
            int j0 = f << 3;
            uint4 va = *(const uint4*)(ag + (size_t)c * NN + n0 + j0);
            float4 r0 = *(const float4*)&g_rinv[brr * NN + n0 + j0];
            float4 r1 = *(const float4*)&g_rinv[brr * NN + n0 + j0 + 4];
            __half2* vh = (__half2*)&va;
            float2 f0 = __half22float2(vh[0]); f0.x *= r0.x; f0.y *= r0.y;
            vh[0] = __float22half2_rn(f0);
            float2 f1 = __half22float2(vh[1]); f1.x *= r0.z; f1.y *= r0.w;
            vh[1] = __float22half2_rn(f1);
            float2 f2 = __half22float2(vh[2]); f2.x *= r1.x; f2.y *= r1.y;
            vh[2] = __float22half2_rn(f2);
            float2 f3 = __half22float2(vh[3]); f3.x *= r1.z; f3.y *= r1.w;
            vh[3] = __float22half2_rn(f3);
            *(uint4*)(Ah + c * AS2 + j0) = va;
            uint4 vb = *(const uint4*)(bg + (size_t)c * NN + n0 + j0);
            *(uint4*)(Bh + c * AS2 + j0) = vb;
        }
        // P1: [64j][128m]
        #pragma unroll
        for (int it = 0; it < 4; it++) {
            int idx = t + (it << 8);
            int j = idx >> 4, f = idx & 15;
            *(uint4*)(P1 + j * PS1 + (f << 3)) =
                *(const uint4*)(Pg + (size_t)(n0 + j) * NN + m0 + (f << 3));
        }
        // P2: [128i][64j]
        #pragma unroll
        for (int it = 0; it < 4; it++) {
            int idx = t + (it << 8);
            int i = idx >> 3, f = idx & 7;
            *(uint4*)(P2 + i * PS2 + (f << 3)) =
                *(const uint4*)(Pg + (size_t)(m0 + i) * NN + n0 + (f << 3));
        }
        __syncthreads();

        int arow = wc + (lane & 15);
        int trow = lane & 15;
        int tcol = wm + ((lane >> 4) << 3);
        int nrow = wm + (lane & 7) + ((lane >> 4) << 3);
        #pragma unroll
        for (int kk = 0; kk < 4; kk++) {
            int acol = (kk << 4) + ((lane >> 4) << 3);
            int ncol = (kk << 4) + (lane & 8);
            // ---- term 1: a~ @ P1 ----
            {
                unsigned ah[2][4], p1[4][2];
                #pragma unroll
                for (int mi = 0; mi < 2; mi++)
                    ldsm4(ah[mi], sptr(Ah + (arow + mi * 16) * AS2 + acol));
                #pragma unroll
                for (int nb = 0; nb < 2; nb++) {
                    unsigned r[4];
                    ldsm4t(r, sptr(P1 + ((kk << 4) + trow) * PS1 + tcol + nb * 16));
                    p1[nb*2][0]=r[0]; p1[nb*2][1]=r[1];
                    p1[nb*2+1][0]=r[2]; p1[nb*2+1][1]=r[3];
                }
                #pragma unroll
                for (int mi = 0; mi < 2; mi++)
                    #pragma unroll
                    for (int ni = 0; ni < 4; ni++)
                        mma_f16(acc1[mi][ni], ah[mi], p1[ni][0], p1[ni][1]);
            }
            // ---- term 2: b' @ P2^T ----
            {
                unsigned bh2[2][4], p2[4][2];
                #pragma unroll
                for (int mi = 0; mi < 2; mi++)
                    ldsm4(bh2[mi], sptr(Bh + (arow + mi * 16) * AS2 + acol));
                #pragma unroll
                for (int nb = 0; nb < 2; nb++) {
                    unsigned r[4];
                    ldsm4(r, sptr(P2 + (nrow + nb * 16) * PS2 + ncol));
                    p2[nb*2][0]=r[0]; p2[nb*2][1]=r[1];
                    p2[nb*2+1][0]=r[2]; p2[nb*2+1][1]=r[3];
                }
                #pragma unroll
                for (int mi = 0; mi < 2; mi++)
                    #pragma unroll
                    for (int ni = 0; ni < 4; ni++)
                        mma_f16(acc2[mi][ni], bh2[mi], p2[ni][0], p2[ni][1]);
            }
        }
    }

    // ---- epilogue: term1 + rinv_m * term2 + bo, de-regionized store ----
    int bb = brr >> 2, rr = brr & 3;
    int hbase = (rr >> 1) << 6, wbase = (rr & 1) << 6;
    int rloc = lane >> 2, cloc = (lane & 3) << 1;
    #pragma unroll
    for (int mi = 0; mi < 2; mi++) {
        int c0 = wc + mi * 16 + rloc, c1 = c0 + 8;
        float bo0 = bo[c0], bo1 = bo[c1];
        #pragma unroll
        for (int ni = 0; ni < 4; ni++) {
            int mcol = wm + ni * 8 + cloc;
            float rv0 = rm[mcol], rv1 = rm[mcol + 1];
            float f0 = acc1[mi][ni][0] + rv0 * acc2[mi][ni][0] + bo0;
            float f1 = acc1[mi][ni][1] + rv1 * acc2[mi][ni][1] + bo0;
            float f2 = acc1[mi][ni][2] + rv0 * acc2[mi][ni][2] + bo1;
            float f3 = acc1[mi][ni][3] + rv1 * acc2[mi][ni][3] + bo1;
            int n = m0 + mcol;
            int h = hbase + (n >> 6), ww = wbase + (n & 63);
            *(float2*)(outp + (((size_t)(bb * 64 + c0)) << 14) + (h << 7) + ww) =
                make_float2(f0, f1);
            *(float2*)(outp + (((size_t)(bb * 64 + c1)) << 14) + (h << 7) + ww) =
                make_float2(f2, f3);
        }
    }
}

// ============================================================================
extern "C" void kernel_launch(void* const* d_in, const int* in_sizes, int n_in,
                              void* d_out, int out_size)
{
    const float* x  = (const float*)d_in[0];
    const float* Wq = (const float*)d_in[1];
    const float* bq = (const float*)d_in[2];
    const float* Wk = (const float*)d_in[3];
    const float* bk = (const float*)d_in[4];
    const float* Wa = (const float*)d_in[5];
    const float* ba = (const float*)d_in[6];
    const float* Wb = (const float*)d_in[7];
    const float* bb = (const float*)d_in[8];
    const float* Wo = (const float*)d_in[9];
    const float* bo = (const float*)d_in[10];

    // score smem: max(2*128*72, 128*136) halves = 36864 B
    cudaFuncSetAttribute(score_kernel,
                         cudaFuncAttributeMaxDynamicSharedMemorySize, 36864);
    cudaFuncSetAttribute(out_kernel,
                         cudaFuncAttributeMaxDynamicSharedMemorySize, 54272);

    combine_w_kernel<<<1, 256>>>(Wo, Wa, ba, Wb, bb);
    conv_kernel<<<512, 256>>>(x, Wq, bq, Wk, bk);
    score_kernel<<<dim3(32, 32, 8), 256, 36864>>>();
    rsum_kernel<<<128, 256>>>();
    out_kernel<<<dim3(32, 8), 256, 54272>>>(bo, (float*)d_out);
}

// round 8
// speedup vs baseline: 7.1302x; 1.1308x over previous
#include <cuda_runtime.h>
#include <cuda_fp16.h>

#define CC   64
#define NN   4096
#define BRN  8
#define HW   128

// ---------------- scratch ----------------
__device__ __half g_q16[BRN * NN * CC];         // q/8, layout [br][n][c]
__device__ __half g_k16[BRN * NN * CC];         // k,   layout [br][m][c]
__device__ __half g_ah[BRN * CC * NN];          // a' = (Wo Wa)x + Wo ba  (later *= rinv)
__device__ __half g_bh[BRN * CC * NN];          // b'
__device__ __half g_P[(size_t)BRN * NN * NN];   // e = exp(S), fp16
__device__ float g_psum[BRN * NN * 32];
__device__ float g_rinv[BRN * NN];
__device__ float g_W2a[CC * CC], g_W2b[CC * CC], g_b2a[CC], g_b2b[CC];

// ---------------- helpers ----------------
__device__ __forceinline__ unsigned sptr(const void* p) {
    return (unsigned)__cvta_generic_to_shared(p);
}
__device__ __forceinline__ void ldsm4(unsigned* r, unsigned a) {
    asm volatile("ldmatrix.sync.aligned.m8n8.x4.shared.b16 {%0,%1,%2,%3},[%4];"
                 : "=r"(r[0]), "=r"(r[1]), "=r"(r[2]), "=r"(r[3]) : "r"(a));
}
__device__ __forceinline__ void ldsm4t(unsigned* r, unsigned a) {
    asm volatile("ldmatrix.sync.aligned.m8n8.x4.trans.shared.b16 {%0,%1,%2,%3},[%4];"
                 : "=r"(r[0]), "=r"(r[1]), "=r"(r[2]), "=r"(r[3]) : "r"(a));
}
__device__ __forceinline__ void mma_f16(float* d, const unsigned* a,
                                        unsigned b0, unsigned b1) {
    asm volatile("mma.sync.aligned.m16n8k16.row.col.f32.f16.f16.f32 "
                 "{%0,%1,%2,%3},{%4,%5,%6,%7},{%8,%9},{%0,%1,%2,%3};"
                 : "+f"(d[0]), "+f"(d[1]), "+f"(d[2]), "+f"(d[3])
                 : "r"(a[0]), "r"(a[1]), "r"(a[2]), "r"(a[3]), "r"(b0), "r"(b1));
}
__device__ __forceinline__ void cp16(unsigned dst, const void* src) {
    asm volatile("cp.async.cg.shared.global [%0], [%1], 16;"
                 :: "r"(dst), "l"(src));
}
__device__ __forceinline__ float fast_exp(float s) {
    s = fminf(fmaxf(s, -87.0f), 87.0f);
    float t = s * 1.4426950408889634f;
    float fl = rintf(t);
    float fr = t - fl;
    float p = 1.5403631e-4f;
    p = fmaf(p, fr, 1.3333558146428443e-3f);
    p = fmaf(p, fr, 9.618129107628477e-3f);
    p = fmaf(p, fr, 5.550410866482158e-2f);
    p = fmaf(p, fr, 2.402265069591007e-1f);
    p = fmaf(p, fr, 6.931471805599453e-1f);
    p = fmaf(p, fr, 1.0f);
    return __int_as_float(((int)fl + 127) << 23) * p;
}

// ============================================================================
// Kernel 0: combined weights  W2a = Wo@Wa, b2a = Wo@ba (likewise b)
// ============================================================================
__global__ __launch_bounds__(256) void combine_w_kernel(
    const float* __restrict__ Wo,
    const float* __restrict__ Wa, const float* __restrict__ ba,
    const float* __restrict__ Wb, const float* __restrict__ bb)
{
    __shared__ float so[4096], sa[4096], sb[4096];
    int t = threadIdx.x;
    for (int i = t; i < 4096; i += 256) { so[i] = Wo[i]; sa[i] = Wa[i]; sb[i] = Wb[i]; }
    __syncthreads();
    for (int e = t; e < 4096; e += 256) {
        int o = e >> 6, c = e & 63;
        float s1 = 0.f, s2 = 0.f;
        for (int k = 0; k < 64; k++) {
            s1 += so[o * 64 + k] * sa[k * 64 + c];
            s2 += so[o * 64 + k] * sb[k * 64 + c];
        }
        g_W2a[e] = s1; g_W2b[e] = s2;
    }
    if (t < 64) {
        float s1 = 0.f, s2 = 0.f;
        for (int k = 0; k < 64; k++) {
            s1 += so[t * 64 + k] * ba[k];
            s2 += so[t * 64 + k] * bb[k];
        }
        g_b2a[t] = s1; g_b2b[t] = s2;
    }
}

// ============================================================================
// Kernel 1: 1x1 convs -> q/8,k fp16 [br][n][c]; a',b' fp16 [br][c][n]
// ============================================================================
__global__ __launch_bounds__(256) void conv_kernel(
    const float* __restrict__ x,
    const float* __restrict__ Wq, const float* __restrict__ bq,
    const float* __restrict__ Wk, const float* __restrict__ bk)
{
    __shared__ float xs[64 * 64];
    int blk = blockIdx.x;
    int br = blk >> 6, chunk = blk & 63;
    int b = br >> 2, r = br & 3;
    int n0 = chunk << 6;
    int h = ((r >> 1) << 6) + chunk;
    int wb = (r & 1) << 6;

    const float* xrow = x + (size_t)(b * CC) * (HW * HW) + (size_t)h * HW + wb;
    for (int idx = threadIdx.x; idx < 64 * 64; idx += 256) {
        int c = idx >> 6, px = idx & 63;
        xs[idx] = xrow[(size_t)c * (HW * HW) + px];
    }
    __syncthreads();

    int px = threadIdx.x & 63;
    int conv = threadIdx.x >> 6;
    const float *W, *bi;
    if      (conv == 0) { W = Wq;    bi = bq;    }
    else if (conv == 1) { W = Wk;    bi = bk;    }
    else if (conv == 2) { W = g_W2a; bi = g_b2a; }
    else                { W = g_W2b; bi = g_b2b; }

    float acc[64];
    #pragma unroll
    for (int o = 0; o < 64; o++) acc[o] = bi[o];
    for (int c = 0; c < 64; c++) {
        float xv = xs[(c << 6) + px];
        #pragma unroll
        for (int o = 0; o < 64; o++) acc[o] += W[o * 64 + c] * xv;
    }

    if (conv < 2) {
        float sc = (conv == 0) ? 0.125f : 1.0f;
        __half* outp = (conv == 0 ? g_q16 : g_k16);
        size_t row = ((size_t)br * NN + n0 + px) * 64;
        #pragma unroll
        for (int o = 0; o < 64; o += 2)
            *(__half2*)(outp + row + o) =
                __float22half2_rn(make_float2(acc[o] * sc, acc[o + 1] * sc));
    } else {
        __half* outp = (conv == 2 ? g_ah : g_bh);
        size_t base = (size_t)br * CC * NN + n0 + px;
        #pragma unroll
        for (int o = 0; o < 64; o++) outp[base + (size_t)o * NN] = __float2half(acc[o]);
    }
}

// ============================================================================
// Kernel 2: e = exp(q.k) single-pass fp16 HMMA; 128x128 tile; smem-staged
//           coalesced fp16 store + deterministic partial row sums.
// ============================================================================
#define QS 72
#define PSS 136
__global__ __launch_bounds__(256, 2) void score_kernel()
{
    extern __shared__ __half smq[];
    __half* QH = smq;               // [128][72]
    __half* KH = smq + 128 * QS;    // [128][72]
    __half* Ps = smq;               // reuse: [128][136] staged e-tile
    __shared__ float pr2[8][64];

    int mt = blockIdx.x, nt = blockIdx.y, brr = blockIdx.z;
    int n0 = nt << 7, m0 = mt << 7;
    int t = threadIdx.x, lane = t & 31, w = t >> 5;
    int wn = (w >> 2) << 6, wm = (w & 3) << 5;

    for (int i = t; i < 512; i += 256) ((float*)pr2)[i] = 0.f;

    #pragma unroll
    for (int it = 0; it < 4; it++) {
        int idx = t + (it << 8);
        int row = idx >> 3, f = idx & 7;
        *(uint4*)(QH + row * QS + (f << 3)) =
            *((const uint4*)(g_q16 + ((size_t)brr * NN + n0 + row) * 64) + f);
        *(uint4*)(KH + row * QS + (f << 3)) =
            *((const uint4*)(g_k16 + ((size_t)brr * NN + m0 + row) * 64) + f);
    }
    __syncthreads();

    float acc[4][4][4];
    #pragma unroll
    for (int i = 0; i < 4; i++)
        #pragma unroll
        for (int j = 0; j < 4; j++)
            #pragma unroll
            for (int k = 0; k < 4; k++) acc[i][j][k] = 0.f;

    int arow = wn + (lane & 15);
    int brow = wm + (lane & 7) + ((lane >> 4) << 3);
    #pragma unroll
    for (int kk = 0; kk < 4; kk++) {
        int acol = (kk << 4) + ((lane >> 4) << 3);
        int bcol = (kk << 4) + (lane & 8);
        unsigned qh[4][4], kh[4][2];
        #pragma unroll
        for (int mi = 0; mi < 4; mi++)
            ldsm4(qh[mi], sptr(QH + (arow + mi * 16) * QS + acol));
        #pragma unroll
        for (int nb = 0; nb < 2; nb++) {
            unsigned r[4];
            ldsm4(r, sptr(KH + (brow + nb * 16) * QS + bcol));
            kh[nb*2][0]=r[0]; kh[nb*2][1]=r[1]; kh[nb*2+1][0]=r[2]; kh[nb*2+1][1]=r[3];
        }
        #pragma unroll
        for (int mi = 0; mi < 4; mi++)
            #pragma unroll
            for (int ni = 0; ni < 4; ni++)
                mma_f16(acc[mi][ni], qh[mi], kh[ni][0], kh[ni][1]);
    }
    __syncthreads();   // QH/KH ldsm reads done; Ps may overwrite

    // exp -> staged smem tile + per-warp row partial sums
    int rloc = lane >> 2;
    int cloc = (lane & 3) << 1;
    #pragma unroll
    for (int mi = 0; mi < 4; mi++) {
        float s0 = 0.f, s1 = 0.f;
        #pragma unroll
        for (int ni = 0; ni < 4; ni++) {
            float e0 = fast_exp(acc[mi][ni][0]);
            float e1 = fast_exp(acc[mi][ni][1]);
            float e2 = fast_exp(acc[mi][ni][2]);
            float e3 = fast_exp(acc[mi][ni][3]);
            s0 += e0 + e1; s1 += e2 + e3;
            int row0 = wn + mi * 16 + rloc;
            int col  = wm + ni * 8 + cloc;
            *(__half2*)(Ps + row0 * PSS + col) =
                __float22half2_rn(make_float2(e0, e1));
            *(__half2*)(Ps + (row0 + 8) * PSS + col) =
                __float22half2_rn(make_float2(e2, e3));
        }
        s0 += __shfl_xor_sync(0xffffffffu, s0, 1);
        s0 += __shfl_xor_sync(0xffffffffu, s0, 2);
        s1 += __shfl_xor_sync(0xffffffffu, s1, 1);
        s1 += __shfl_xor_sync(0xffffffffu, s1, 2);
        if ((lane & 3) == 0) {
            pr2[w][mi * 16 + rloc]     = pr2[w][mi * 16 + rloc] + s0;
            pr2[w][mi * 16 + rloc + 8] = pr2[w][mi * 16 + rloc + 8] + s1;
        }
    }
    __syncthreads();

    // coalesced global store of the e-tile
    size_t Pbase = (size_t)brr * NN * NN;
    #pragma unroll
    for (int it = 0; it < 8; it++) {
        int idx = t + (it << 8);
        int row = idx >> 4, f = idx & 15;
        *(uint4*)(g_P + Pbase + (size_t)(n0 + row) * NN + m0 + (f << 3)) =
            *(uint4*)(Ps + row * PSS + (f << 3));
    }
    if (t < 128) {
        int g4 = (t >> 6) << 2, lr = t & 63;
        float s = pr2[g4][lr] + pr2[g4+1][lr] + pr2[g4+2][lr] + pr2[g4+3][lr];
        g_psum[((size_t)brr * NN + n0 + t) * 32 + mt] = s;
    }
}

// ============================================================================
// Kernel 3: rinv[row] = 1 / sum_mt psum[row][mt]
// ============================================================================
__global__ __launch_bounds__(256) void rsum_kernel()
{
    int i = blockIdx.x * 256 + threadIdx.x;
    if (i < BRN * NN) {
        const float4* p = (const float4*)(g_psum + (size_t)i * 32);
        float s = 0.f;
        #pragma unroll
        for (int k = 0; k < 8; k++) {
            float4 v = p[k];
            s += v.x + v.y + v.z + v.w;
        }
        g_rinv[i] = 1.f / s;
    }
}

// ============================================================================
// Kernel 3.5: g_ah[br][c][n] *= rinv[br*NN + n]  (in place, once per launch)
// ============================================================================
__global__ __launch_bounds__(256) void scale_a_kernel()
{
    int g = (blockIdx.x * 256 + threadIdx.x) << 3;   // half index, 8 per thread
    int br = g >> 18;
    int n = g & (NN - 1);
    uint4 va = *(const uint4*)(g_ah + g);
    float4 r0 = *(const float4*)&g_rinv[br * NN + n];
    float4 r1 = *(const float4*)&g_rinv[br * NN + n + 4];
    __half2* vh = (__half2*)&va;
    float2 f0 = __half22float2(vh[0]); f0.x *= r0.x; f0.y *= r0.y;
    vh[0] = __float22half2_rn(f0);
    float2 f1 = __half22float2(vh[1]); f1.x *= r0.z; f1.y *= r0.w;
    vh[1] = __float22half2_rn(f1);
    float2 f2 = __half22float2(vh[2]); f2.x *= r1.x; f2.y *= r1.y;
    vh[2] = __float22half2_rn(f2);
    float2 f3 = __half22float2(vh[3]); f3.x *= r1.z; f3.y *= r1.w;
    vh[3] = __float22half2_rn(f3);
    *(uint4*)(g_ah + g) = va;
}

// ============================================================================
// Kernel 4: out[c,m] = A@e + rinv_m*(b'@e^T) + bo; cp.async 2-stage pipeline.
// 64c x 128m tile, 256 thr, K-chunks of 64, double-buffered smem.
// ============================================================================
#define AS2 72
#define PS1 136
#define PS2 72
#define STAGE_B 54272   // bytes per stage: 2*64*72*2 + 64*136*2 + 128*72*2

__global__ __launch_bounds__(256, 1) void out_kernel(
    const float* __restrict__ bo, float* __restrict__ outp)
{
    extern __shared__ char smo[];
    __shared__ float rm[128];

    int mt = blockIdx.x, brr = blockIdx.y;
    int m0 = mt << 7;
    int t = threadIdx.x, lane = t & 31, w = t >> 5;
    int wc = (w >> 2) << 5, wm = (w & 3) << 5;

    const __half* ag = g_ah + (size_t)brr * CC * NN;
    const __half* bg = g_bh + (size_t)brr * CC * NN;
    const __half* Pg = g_P + (size_t)brr * NN * NN;

    if (t < 128) rm[t] = g_rinv[brr * NN + m0 + t];

    // per-thread fill indices (constant across chunks)
    int fc  = t >> 3, ff  = t & 7;       // A/B: rows 0..31 (+32 on it=1), 8 uint4/row
    int pj  = t >> 4, pf  = t & 15;      // P1: rows 0..15 (+16/it), 16 uint4/row
    int qi  = t >> 3, qf  = t & 7;       // P2: rows 0..31 (+32/it), 8 uint4/row

    unsigned sb = sptr(smo);

    float acc1[2][4][4], acc2[2][4][4];
    #pragma unroll
    for (int i = 0; i < 2; i++)
        #pragma unroll
        for (int j = 0; j < 4; j++)
            #pragma unroll
            for (int k = 0; k < 4; k++) { acc1[i][j][k] = 0.f; acc2[i][j][k] = 0.f; }

    // ---- fill stage s with chunk kt ----
    auto fill = [&](int kt, int s) {
        int n0 = kt << 6;
        unsigned base = sb + s * STAGE_B;
        unsigned A0 = base;
        unsigned B0 = base + 64 * AS2 * 2;
        unsigned P10 = B0 + 64 * AS2 * 2;
        unsigned P20 = P10 + 64 * PS1 * 2;
        #pragma unroll
        for (int it = 0; it < 2; it++) {
            int c = fc + (it << 5);
            cp16(A0 + (c * AS2 + (ff << 3)) * 2, ag + (size_t)c * NN + n0 + (ff << 3));
            cp16(B0 + (c * AS2 + (ff << 3)) * 2, bg + (size_t)c * NN + n0 + (ff << 3));
        }
        #pragma unroll
        for (int it = 0; it < 4; it++) {
            int j = pj + (it << 4);
            cp16(P10 + (j * PS1 + (pf << 3)) * 2,
                 Pg + (size_t)(n0 + j) * NN + m0 + (pf << 3));
        }
        #pragma unroll
        for (int it = 0; it < 4; it++) {
            int i2 = qi + (it << 5);
            cp16(P20 + (i2 * PS2 + (qf << 3)) * 2,
                 Pg + (size_t)(m0 + i2) * NN + n0 + (qf << 3));
        }
        asm volatile("cp.async.commit_group;");
    };

    fill(0, 0);

    for (int kt = 0; kt < 64; kt++) {
        int st = kt & 1;
        if (kt < 63) {
            fill(kt + 1, st ^ 1);
            asm volatile("cp.async.wait_group 1;");
        } else {
            asm volatile("cp.async.wait_group 0;");
        }
        __syncthreads();

        const __half* Ah = (const __half*)(smo + st * STAGE_B);
        const __half* Bh = Ah + 64 * AS2;
        const __half* P1 = Bh + 64 * AS2;
        const __half* P2 = P1 + 64 * PS1;

        int arow = wc + (lane & 15);
        int trow = lane & 15;
        int tcol = wm + ((lane >> 4) << 3);
        int nrow = wm + (lane & 7) + ((lane >> 4) << 3);
        #pragma unroll
        for (int kk = 0; kk < 4; kk++) {
            int acol = (kk << 4) + ((lane >> 4) << 3);
            int ncol = (kk << 4) + (lane & 8);
            // ---- term 1: A @ P1 ----
            {
                unsigned ah[2][4], p1[4][2];
                #pragma unroll
                for (int mi = 0; mi < 2; mi++)
                    ldsm4(ah[mi], sptr(Ah + (arow + mi * 16) * AS2 + acol));
                #pragma unroll
                for (int nb = 0; nb < 2; nb++) {
                    unsigned r[4];
                    ldsm4t(r, sptr(P1 + ((kk << 4) + trow) * PS1 + tcol + nb * 16));
                    p1[nb*2][0]=r[0]; p1[nb*2][1]=r[1];
                    p1[nb*2+1][0]=r[2]; p1[nb*2+1][1]=r[3];
                }
                #pragma unroll
                for (int mi = 0; mi < 2; mi++)
                    #pragma unroll
                    for (int ni = 0; ni < 4; ni++)
                        mma_f16(acc1[mi][ni], ah[mi], p1[ni][0], p1[ni][1]);
            }
            // ---- term 2: b' @ P2^T ----
            {
                unsigned bh2[2][4], p2[4][2];
                #pragma unroll
                for (int mi = 0; mi < 2; mi++)
                    ldsm4(bh2[mi], sptr(Bh + (arow + mi * 16) * AS2 + acol));
                #pragma unroll
                for (int nb = 0; nb < 2; nb++) {
                    unsigned r[4];
                    ldsm4(r, sptr(P2 + (nrow + nb * 16) * PS2 + ncol));
                    p2[nb*2][0]=r[0]; p2[nb*2][1]=r[1];
                    p2[nb*2+1][0]=r[2]; p2[nb*2+1][1]=r[3];
                }
                #pragma unroll
                for (int mi = 0; mi < 2; mi++)
                    #pragma unroll
                    for (int ni = 0; ni < 4; ni++)
                        mma_f16(acc2[mi][ni], bh2[mi], p2[ni][0], p2[ni][1]);
            }
        }
        __syncthreads();
    }

    // ---- epilogue: term1 + rinv_m * term2 + bo, de-regionized store ----
    int bb = brr >> 2, rr = brr & 3;
    int hbase = (rr >> 1) << 6, wbase = (rr & 1) << 6;
    int rloc = lane >> 2, cloc = (lane & 3) << 1;
    #pragma unroll
    for (int mi = 0; mi < 2; mi++) {
        int c0 = wc + mi * 16 + rloc, c1 = c0 + 8;
        float bo0 = bo[c0], bo1 = bo[c1];
        #pragma unroll
        for (int ni = 0; ni < 4; ni++) {
            int mcol = wm + ni * 8 + cloc;
            float rv0 = rm[mcol], rv1 = rm[mcol + 1];
            float f0 = acc1[mi][ni][0] + rv0 * acc2[mi][ni][0] + bo0;
            float f1 = acc1[mi][ni][1] + rv1 * acc2[mi][ni][1] + bo0;
            float f2 = acc1[mi][ni][2] + rv0 * acc2[mi][ni][2] + bo1;
            float f3 = acc1[mi][ni][3] + rv1 * acc2[mi][ni][3] + bo1;
            int n = m0 + mcol;
            int h = hbase + (n >> 6), ww = wbase + (n & 63);
            *(float2*)(outp + (((size_t)(bb * 64 + c0)) << 14) + (h << 7) + ww) =
                make_float2(f0, f1);
            *(float2*)(outp + (((size_t)(bb * 64 + c1)) << 14) + (h << 7) + ww) =
                make_float2(f2, f3);
        }
    }
}

// ============================================================================
extern "C" void kernel_launch(void* const* d_in, const int* in_sizes, int n_in,
                              void* d_out, int out_size)
{
    const float* x  = (const float*)d_in[0];
    const float* Wq = (const float*)d_in[1];
    const float* bq = (const float*)d_in[2];
    const float* Wk = (const float*)d_in[3];
    const float* bk = (const float*)d_in[4];
    const float* Wa = (const float*)d_in[5];
    const float* ba = (const float*)d_in[6];
    const float* Wb = (const float*)d_in[7];
    const float* bb = (const float*)d_in[8];
    const float* Wo = (const float*)d_in[9];
    const float* bo = (const float*)d_in[10];

    cudaFuncSetAttribute(score_kernel,
                         cudaFuncAttributeMaxDynamicSharedMemorySize, 36864);
    cudaFuncSetAttribute(out_kernel,
                         cudaFuncAttributeMaxDynamicSharedMemorySize, 2 * STAGE_B);

    combine_w_kernel<<<1, 256>>>(Wo, Wa, ba, Wb, bb);
    conv_kernel<<<512, 256>>>(x, Wq, bq, Wk, bk);
    score_kernel<<<dim3(32, 32, 8), 256, 36864>>>();
    rsum_kernel<<<128, 256>>>();
    scale_a_kernel<<<1024, 256>>>();
    out_kernel<<<dim3(32, 8), 256, 2 * STAGE_B>>>(bo, (float*)d_out);
}